// round 12
// baseline (speedup 1.0000x reference)
#include <cuda_runtime.h>
#include <cuda_fp16.h>
#include <cstdint>

// Problem constants (fixed by the reference)
#define NN   50000
#define EE   800000
#define DD   128
#define HH   8
#define CC   16
#define EDD  64
#define LL   3

// ---------------- scratch (static device globals; no allocation) -------------
__device__ float  g_q  [NN * DD];
__device__ float  g_k  [NN * DD];
__device__ float  g_v  [NN * DD];
__device__ float  g_out[NN * DD];     // skip (x@Ws+bs), then final pre-BN out
__device__ __half g_xh [NN * DD];     // x split hi
__device__ __half g_xl [NN * DD];     // x split lo
__device__ __half g_e  [(size_t)EE * DD];      // per-edge e (fp16, CSR order)
__device__ __half g_ea16[(size_t)EE * EDD];    // edge_attr fp16, CSR-permuted
__device__ __half g_wet [DD * EDD];            // We^T fp16 [n=128][k=64]
__device__ __half g_wallh[512 * DD];           // [Wq|Wk|Wv|Ws]^T hi
__device__ __half g_walll[512 * DD];           // lo part
__device__ float  g_ball [512];                // [bq|bk|bv|bs]
__device__ float  g_alpha[(size_t)EE * HH];    // raw scores (CSR order)
__device__ int    g_nmax[NN * HH];             // ordered-int encoded per-(node,head) max
__device__ double g_sums[2 * DD];
__device__ float2 g_ab  [DD];
// CSR (dst-sorted edge order; edge_index is launch-constant)
__device__ int    g_deg   [NN];
__device__ int    g_cursor[NN];
__device__ int    g_rowptr[NN + 1];
__device__ int    g_eord  [EE];
__device__ int    g_srcp  [EE];      // src per CSR position
__device__ int    g_dstp  [EE];      // dst per CSR position
__device__ int    g_bsums [256];

// ---------------- helpers ----------------------------------------------------
__device__ __forceinline__ uint32_t smem_u32(const void* p) {
    uint32_t a;
    asm("{ .reg .u64 t; cvta.to.shared.u64 t, %1; cvt.u32.u64 %0, t; }" : "=r"(a) : "l"(p));
    return a;
}
__device__ __forceinline__ uint32_t sw128(uint32_t off) { return off ^ ((off >> 3) & 0x70); }
__device__ __forceinline__ uint32_t sw64 (uint32_t off) { return off ^ ((off >> 3) & 0x30); }

__device__ __forceinline__ void ldmatrix_x4(uint32_t* r, uint32_t addr) {
    asm volatile("ldmatrix.sync.aligned.m8n8.x4.shared.b16 {%0,%1,%2,%3}, [%4];"
                 : "=r"(r[0]), "=r"(r[1]), "=r"(r[2]), "=r"(r[3]) : "r"(addr));
}
__device__ __forceinline__ void mma16816(float* c, const uint32_t* a, const uint32_t* b) {
    asm volatile("mma.sync.aligned.m16n8k16.row.col.f32.f16.f16.f32 "
                 "{%0,%1,%2,%3}, {%4,%5,%6,%7}, {%8,%9}, {%0,%1,%2,%3};"
                 : "+f"(c[0]), "+f"(c[1]), "+f"(c[2]), "+f"(c[3])
                 : "r"(a[0]), "r"(a[1]), "r"(a[2]), "r"(a[3]), "r"(b[0]), "r"(b[1]));
}

// ---------------- CSR build (once per launch) ----------------------------------
__global__ void csr_zero() {
    int i = blockIdx.x * blockDim.x + threadIdx.x;
    if (i < NN) { g_deg[i] = 0; g_cursor[i] = 0; }
}
__global__ void csr_hist(const int* __restrict__ ei) {
    int e = blockIdx.x * blockDim.x + threadIdx.x;
    if (e < EE) atomicAdd(&g_deg[ei[EE + e]], 1);
}
__global__ void csr_scan1() {
    __shared__ int s[256];
    int t = threadIdx.x;
    int i = blockIdx.x * 256 + t;
    int v = (i < NN) ? g_deg[i] : 0;
    s[t] = v;
    __syncthreads();
    for (int st = 1; st < 256; st <<= 1) {
        int x = (t >= st) ? s[t - st] : 0;
        __syncthreads();
        if (t >= st) s[t] += x;
        __syncthreads();
    }
    if (i < NN) g_rowptr[i] = s[t] - v;
    if (t == 255) g_bsums[blockIdx.x] = s[255];
}
__global__ void csr_scan2(int nblocks) {      // parallel exclusive scan of block sums
    __shared__ int s[256];
    int t = threadIdx.x;
    int v = (t < nblocks) ? g_bsums[t] : 0;
    s[t] = v;
    __syncthreads();
    for (int st = 1; st < 256; st <<= 1) {
        int x = (t >= st) ? s[t - st] : 0;
        __syncthreads();
        if (t >= st) s[t] += x;
        __syncthreads();
    }
    if (t < nblocks) g_bsums[t] = s[t] - v;
}
__global__ void csr_scan3() {
    int i = blockIdx.x * blockDim.x + threadIdx.x;
    if (i < NN) g_rowptr[i] += g_bsums[i >> 8];
    if (i == 0) g_rowptr[NN] = EE;
}
__global__ void csr_fill(const int* __restrict__ ei) {
    int e = blockIdx.x * blockDim.x + threadIdx.x;
    if (e >= EE) return;
    int d = ei[EE + e];
    int pos = g_rowptr[d] + atomicAdd(&g_cursor[d], 1);
    g_eord[pos] = e;
}
__global__ void perm_idx_kernel(const int* __restrict__ ei) {
    int p = blockIdx.x * blockDim.x + threadIdx.x;
    if (p >= EE) return;
    int eid = g_eord[p];
    g_srcp[p] = ei[eid];
    g_dstp[p] = ei[EE + eid];
}
// edge_attr -> fp16, permuted into CSR order
__global__ void conv_ea_perm(const float* __restrict__ ea) {
    int i = blockIdx.x * blockDim.x + threadIdx.x;   // over 4-float units
    int p = i >> 4;
    if (p >= EE) return;
    int off = (i & 15) * 4;
    int eid = g_eord[p];
    float4 f = *(const float4*)(ea + (size_t)eid * EDD + off);
    __half2 h01 = __floats2half2_rn(f.x, f.y);
    __half2 h23 = __floats2half2_rn(f.z, f.w);
    uint2 pk;
    pk.x = *(const unsigned*)&h01;
    pk.y = *(const unsigned*)&h23;
    *(uint2*)(g_ea16 + (size_t)p * EDD + off) = pk;
}

// ---------------- one-time / per-layer prep ------------------------------------
__global__ void xsplit0_kernel(const float* __restrict__ x) {
    int i = blockIdx.x * blockDim.x + threadIdx.x;
    if (i >= NN * DD) return;
    float f = x[i];
    __half h = __float2half(f);
    g_xh[i] = h;
    g_xl[i] = __float2half(f - __half2float(h));
}

__global__ void wet_kernel(const float* __restrict__ We) {
    int i = blockIdx.x * blockDim.x + threadIdx.x;
    if (i >= DD * EDD) return;
    int n = i / EDD, k = i % EDD;
    g_wet[i] = __float2half(We[k * DD + n]);
}

__global__ void wall_prep_kernel(const float* __restrict__ Wq, const float* __restrict__ Wk,
                                 const float* __restrict__ Wv, const float* __restrict__ Ws,
                                 const float* __restrict__ bq, const float* __restrict__ bk,
                                 const float* __restrict__ bv, const float* __restrict__ bs) {
    int i = blockIdx.x * blockDim.x + threadIdx.x;
    if (i >= 512 * DD) return;
    int ng = i / DD;
    int k  = i % DD;
    int mtx = ng >> 7, nloc = ng & 127;
    const float* W = (mtx == 0) ? Wq : (mtx == 1) ? Wk : (mtx == 2) ? Wv : Ws;
    float w = W[k * DD + nloc];
    __half h = __float2half(w);
    g_wallh[i] = h;
    g_walll[i] = __float2half(w - __half2float(h));
    if (i < 512) {
        int m2 = i >> 7, l2 = i & 127;
        const float* b = (m2 == 0) ? bq : (m2 == 1) ? bk : (m2 == 2) ? bv : bs;
        g_ball[i] = b[l2];
    }
}

__global__ void init_kernel() {
    int i = blockIdx.x * blockDim.x + threadIdx.x;
    if (i < NN * HH) g_nmax[i] = (int)0x807FFFFF;   // encoded -inf
    if (i < 2 * DD)  g_sums[i] = 0.0;
}

// ------------- fused node GEMM (split-fp16 HMMA): [q|k|v|skip] -----------------
__global__ void __launch_bounds__(256, 2)
node_gemm_mma(float* __restrict__ oq, float* __restrict__ okk,
              float* __restrict__ ov, float* __restrict__ os) {
    __shared__ __align__(128) __half sAh[128 * 32];
    __shared__ __align__(128) __half sAl[128 * 32];
    __shared__ __align__(128) __half sBh[128 * 32];
    __shared__ __align__(128) __half sBl[128 * 32];
    __shared__ float sbias[128];

    const int tid  = threadIdx.x;
    const int wid  = tid >> 5;
    const int lane = tid & 31;
    const int ntile = blockIdx.x & 3;
    const int mbase = (blockIdx.x >> 2) * 128;

    if (tid < 128) sbias[tid] = g_ball[ntile * 128 + tid];

    float acc[16][4];
#pragma unroll
    for (int i = 0; i < 16; i++)
#pragma unroll
        for (int j = 0; j < 4; j++) acc[i][j] = 0.0f;

    const uint32_t sAhu = smem_u32(sAh);
    const uint32_t sAlu = smem_u32(sAl);
    const uint32_t sBhu = smem_u32(sBh);
    const uint32_t sBlu = smem_u32(sBl);
    const int mrow = wid * 16;

    for (int kc = 0; kc < 4; kc++) {
#pragma unroll
        for (int i = 0; i < 2; i++) {
            int idx = i * 256 + tid;
            int row = idx >> 2, unit = idx & 3;
            int grow = mbase + row;
            uint4 vh = make_uint4(0, 0, 0, 0), vl = make_uint4(0, 0, 0, 0);
            if (grow < NN) {
                size_t g = (size_t)grow * DD + kc * 32 + unit * 8;
                vh = *(const uint4*)(g_xh + g);
                vl = *(const uint4*)(g_xl + g);
            }
            *(uint4*)((char*)sAh + sw64(idx * 16)) = vh;
            *(uint4*)((char*)sAl + sw64(idx * 16)) = vl;
        }
#pragma unroll
        for (int i = 0; i < 2; i++) {
            int idx = i * 256 + tid;
            int row = idx >> 2, unit = idx & 3;
            size_t g = (size_t)(ntile * 128 + row) * DD + kc * 32 + unit * 8;
            *(uint4*)((char*)sBh + sw64(idx * 16)) = *(const uint4*)(g_wallh + g);
            *(uint4*)((char*)sBl + sw64(idx * 16)) = *(const uint4*)(g_walll + g);
        }
        __syncthreads();

#pragma unroll
        for (int t = 0; t < 2; t++) {
            uint32_t ah[4], al[4];
            uint32_t aoff = (uint32_t)(mrow + (lane & 15)) * 64 + t * 32 + ((lane >> 4) * 16);
            ldmatrix_x4(ah, sAhu + sw64(aoff));
            ldmatrix_x4(al, sAlu + sw64(aoff));
#pragma unroll
            for (int np = 0; np < 8; np++) {
                int mtx = lane >> 3;
                uint32_t boff = (uint32_t)(np * 16 + ((mtx >> 1) * 8) + (lane & 7)) * 64
                              + t * 32 + ((mtx & 1) * 16);
                uint32_t bh[4], bl[4];
                ldmatrix_x4(bh, sBhu + sw64(boff));
                ldmatrix_x4(bl, sBlu + sw64(boff));
                mma16816(acc[2 * np],     ah, bh);
                mma16816(acc[2 * np],     ah, bl);
                mma16816(acc[2 * np],     al, bh);
                mma16816(acc[2 * np + 1], ah, bh + 2);
                mma16816(acc[2 * np + 1], ah, bl + 2);
                mma16816(acc[2 * np + 1], al, bh + 2);
            }
        }
        __syncthreads();
    }

    float* dst = (ntile == 0) ? oq : (ntile == 1) ? okk : (ntile == 2) ? ov : os;
    const int r0 = mbase + mrow + (lane >> 2);
    const int cq = (lane & 3) * 2;
#pragma unroll
    for (int nt = 0; nt < 16; nt++) {
        int n = nt * 8 + cq;
        float b0 = sbias[n], b1 = sbias[n + 1];
        if (r0 < NN)
            *(float2*)(dst + (size_t)r0 * DD + n) = make_float2(acc[nt][0] + b0, acc[nt][1] + b1);
        if (r0 + 8 < NN)
            *(float2*)(dst + (size_t)(r0 + 8) * DD + n) = make_float2(acc[nt][2] + b0, acc[nt][3] + b1);
    }
}

// -------- edge GEMM (CSR order) + e store + fused alpha + segment max ----------
__global__ void __launch_bounds__(256, 2)
edge_gemm_mma(const float* __restrict__ bias) {
    __shared__ __align__(128) __half sA[128 * 64];
    __shared__ __align__(128) __half sB[128 * 64];
    __shared__ float sbias[128];

    const int tid  = threadIdx.x;
    const int wid  = tid >> 5;
    const int lane = tid & 31;
    const size_t tile = blockIdx.x;

    if (tid < 128) sbias[tid] = bias[tid];

    const uint4* Ag = (const uint4*)(g_ea16 + tile * 128 * EDD);
#pragma unroll
    for (int i = 0; i < 4; i++) {
        int idx = i * 256 + tid;
        uint4 val = Ag[idx];
        *(uint4*)((char*)sA + sw128(idx * 16)) = val;
    }
    const uint4* Bg = (const uint4*)g_wet;
#pragma unroll
    for (int i = 0; i < 4; i++) {
        int idx = i * 256 + tid;
        uint4 val = Bg[idx];
        *(uint4*)((char*)sB + sw128(idx * 16)) = val;
    }
    __syncthreads();

    const uint32_t sAu = smem_u32(sA);
    const uint32_t sBu = smem_u32(sB);
    const int mrow = wid * 16;

    uint32_t afrag[4][4];
#pragma unroll
    for (int t = 0; t < 4; t++) {
        uint32_t off = (uint32_t)(mrow + (lane & 15)) * 128 + t * 32 + ((lane >> 4) * 16);
        ldmatrix_x4(afrag[t], sAu + sw128(off));
    }

    float acc[16][4];
#pragma unroll
    for (int i = 0; i < 16; i++)
#pragma unroll
        for (int j = 0; j < 4; j++) acc[i][j] = 0.0f;

#pragma unroll
    for (int t = 0; t < 4; t++) {
#pragma unroll
        for (int np = 0; np < 8; np++) {
            int mtx = lane >> 3;
            int n   = np * 16 + ((mtx >> 1) * 8) + (lane & 7);
            int kb  = t * 32 + ((mtx & 1) * 16);
            uint32_t b[4];
            ldmatrix_x4(b, sBu + sw128((uint32_t)n * 128 + kb));
            mma16816(acc[2 * np],     afrag[t], b);
            mma16816(acc[2 * np + 1], afrag[t], b + 2);
        }
    }

    const int p0 = (int)tile * 128 + mrow + (lane >> 2);
    const int p1 = p0 + 8;
    const int cq = (lane & 3) * 2;
    const int src0 = g_srcp[p0], dst0 = g_dstp[p0];
    const int src1 = g_srcp[p1], dst1 = g_dstp[p1];
    const float* q0 = g_q + (size_t)dst0 * DD;
    const float* k0 = g_k + (size_t)src0 * DD;
    const float* q1 = g_q + (size_t)dst1 * DD;
    const float* k1 = g_k + (size_t)src1 * DD;
    __half* e0p = g_e + (size_t)p0 * DD;
    __half* e1p = g_e + (size_t)p1 * DD;

    float ps0[8], ps1[8];
#pragma unroll
    for (int h = 0; h < 8; h++) { ps0[h] = 0.0f; ps1[h] = 0.0f; }

#pragma unroll
    for (int nt = 0; nt < 16; nt++) {
        int n = nt * 8 + cq;
        int h = nt >> 1;
        float b0 = sbias[n], b1 = sbias[n + 1];
        float ea0 = acc[nt][0] + b0, ea1 = acc[nt][1] + b1;
        float eb0 = acc[nt][2] + b0, eb1 = acc[nt][3] + b1;
        *(__half2*)(e0p + n) = __floats2half2_rn(ea0, ea1);
        *(__half2*)(e1p + n) = __floats2half2_rn(eb0, eb1);
        float2 qa = *(const float2*)(q0 + n);
        float2 ka = *(const float2*)(k0 + n);
        float2 qb = *(const float2*)(q1 + n);
        float2 kb = *(const float2*)(k1 + n);
        ps0[h] += qa.x * (ka.x + ea0) + qa.y * (ka.y + ea1);
        ps1[h] += qb.x * (kb.x + eb0) + qb.y * (kb.y + eb1);
    }
#pragma unroll
    for (int h = 0; h < 8; h++) {
        ps0[h] += __shfl_xor_sync(0xFFFFFFFFu, ps0[h], 1);
        ps0[h] += __shfl_xor_sync(0xFFFFFFFFu, ps0[h], 2);
        ps1[h] += __shfl_xor_sync(0xFFFFFFFFu, ps1[h], 1);
        ps1[h] += __shfl_xor_sync(0xFFFFFFFFu, ps1[h], 2);
    }
    const int qid = lane & 3;
#pragma unroll
    for (int h = 0; h < 8; h++) {
        if ((h & 3) == qid) {
            float a0 = ps0[h] * 0.25f;
            g_alpha[(size_t)p0 * HH + h] = a0;
            int rep = __float_as_int(a0);
            rep = (rep >= 0) ? rep : (rep ^ 0x7FFFFFFF);
            atomicMax(&g_nmax[dst0 * HH + h], rep);
            float a1 = ps1[h] * 0.25f;
            g_alpha[(size_t)p1 * HH + h] = a1;
            rep = __float_as_int(a1);
            rep = (rep >= 0) ? rep : (rep ^ 0x7FFFFFFF);
            atomicMax(&g_nmax[dst1 * HH + h], rep);
        }
    }
}

// ------------- per-node gather: softmax + message sum + skip add ---------------
// alpha/e sequential (CSR order); per-head max precomputed via atomicMax.
__global__ void __launch_bounds__(128)
gather_kernel() {
    const int n   = blockIdx.x;
    const int tid = threadIdx.x;
    const int start = g_rowptr[n], end = g_rowptr[n + 1];
    const int i0 = tid >> 3, h8 = tid & 7;
    const int hch = tid >> 4;

    __shared__ float samax[8];
    __shared__ float sex[16][8];
    __shared__ int   ssrc[16];
    __shared__ float sden[8];
    __shared__ __align__(16) float  sV[16 * 128];   // 8 KB
    __shared__ __align__(16) __half sE[16 * 128];   // 4 KB

    if (tid < 8) {
        int enc = g_nmax[n * HH + tid];
        enc = (enc >= 0) ? enc : (enc ^ 0x7FFFFFFF);
        samax[tid] = __int_as_float(enc);
    }
    __syncthreads();
    const float amax = samax[h8];

    float msg = 0.0f, den = 0.0f;
    for (int base = start; base < end; base += 16) {
        int cnt = min(16, end - base);
        if (tid < cnt) ssrc[tid] = g_srcp[base + tid];
        if (i0 < cnt)
            sex[i0][h8] = __expf(g_alpha[(size_t)(base + i0) * HH + h8] - amax);
        __syncthreads();   // ssrc ready

        // stage e rows: cnt*16 uint4, fully linear from g_e + base*DD
        {
            const uint4* src = (const uint4*)(g_e + (size_t)base * DD);
            uint4* dst = (uint4*)sE;
            for (int u = tid; u < cnt * 16; u += 128) dst[u] = src[u];
        }
        // stage v rows: cnt*32 uint4, gathered per row
        {
            uint4* dst = (uint4*)sV;
            for (int u = tid; u < cnt * 32; u += 128) {
                int row = u >> 5, c = u & 31;
                dst[u] = ((const uint4*)(g_v + (size_t)ssrc[row] * DD))[c];
            }
        }
        __syncthreads();   // staged data ready

#pragma unroll 4
        for (int i = 0; i < cnt; i++) {
            float ex = sex[i][hch];
            msg += (sV[i * 128 + tid] + __half2float(sE[i * 128 + tid])) * ex;
        }
        if (tid < 8) {
            float s = 0.0f;
            for (int i = 0; i < cnt; i++) s += sex[i][tid];
            den += s;
        }
        __syncthreads();   // protect sex/ssrc for next chunk
    }
    if (tid < 8) sden[tid] = den;
    __syncthreads();

    float o = msg / (sden[hch] + 1e-16f) + g_out[(size_t)n * DD + tid];
    g_out[(size_t)n * DD + tid] = o;
}

// ---- BN column sums (fp64) -----------------------------------------------------
__global__ void bn_sum_kernel() {
    int ch = threadIdx.x;
    double s = 0.0, s2 = 0.0;
    for (int r = blockIdx.x; r < NN; r += gridDim.x) {
        float v = g_out[(size_t)r * DD + ch];
        s  += (double)v;
        s2 += (double)v * (double)v;
    }
    atomicAdd(&g_sums[ch], s);
    atomicAdd(&g_sums[DD + ch], s2);
}

__global__ void bn_fin_kernel(const float* __restrict__ gamma,
                              const float* __restrict__ beta) {
    int ch = threadIdx.x;
    double mu  = g_sums[ch] / (double)NN;
    double var = g_sums[DD + ch] / (double)NN - mu * mu;
    double rs  = 1.0 / sqrt(var + 1e-5);
    float a = gamma[ch] * (float)rs;
    float b = beta[ch] - (float)mu * a;
    g_ab[ch] = make_float2(a, b);
}

__global__ void bn_apply_kernel(float* __restrict__ xo, int write_f32) {
    int idx = blockIdx.x * blockDim.x + threadIdx.x;
    if (idx >= NN * DD) return;
    int ch = idx & (DD - 1);
    float2 c = g_ab[ch];
    float y = g_out[idx] * c.x + c.y;
    y = (y >= 0.0f) ? y : 0.01f * y;
    __half h = __float2half(y);
    g_xh[idx] = h;
    g_xl[idx] = __float2half(y - __half2float(h));
    if (write_f32) xo[idx] = y;
}

// ---------------- driver -------------------------------------------------------
extern "C" void kernel_launch(void* const* d_in, const int* in_sizes, int n_in,
                              void* d_out, int out_size) {
    const float* x     = (const float*)d_in[0];
    const int*   ei    = (const int*)  d_in[1];
    const float* ea    = (const float*)d_in[2];
    const float* Wq    = (const float*)d_in[3];
    const float* bq    = (const float*)d_in[4];
    const float* Wk    = (const float*)d_in[5];
    const float* bk    = (const float*)d_in[6];
    const float* Wv    = (const float*)d_in[7];
    const float* bv    = (const float*)d_in[8];
    const float* We    = (const float*)d_in[9];
    const float* be    = (const float*)d_in[10];
    const float* Ws    = (const float*)d_in[11];
    const float* bs    = (const float*)d_in[12];
    const float* gamma = (const float*)d_in[13];
    const float* beta  = (const float*)d_in[14];
    float* out = (float*)d_out;

    float *q, *k, *v, *ob;
    cudaGetSymbolAddress((void**)&q,  g_q);
    cudaGetSymbolAddress((void**)&k,  g_k);
    cudaGetSymbolAddress((void**)&v,  g_v);
    cudaGetSymbolAddress((void**)&ob, g_out);

    const int edgeTiles      = EE / 128;                // 6250
    const int nodeGemmBlocks = ((NN + 127) / 128) * 4;  // 1564
    const int nodeB          = (NN + 255) / 256;        // 196

    // one-time per launch: CSR build, permutation, conversions
    csr_zero <<<nodeB, 256>>>();
    csr_hist <<<(EE + 255) / 256, 256>>>(ei);
    csr_scan1<<<nodeB, 256>>>();
    csr_scan2<<<1, 256>>>(nodeB);
    csr_scan3<<<nodeB, 256>>>();
    csr_fill <<<(EE + 255) / 256, 256>>>(ei);
    perm_idx_kernel<<<(EE + 255) / 256, 256>>>(ei);
    conv_ea_perm<<<(int)(((size_t)EE * 16 + 255) / 256), 256>>>(ea);
    xsplit0_kernel<<<(NN * DD + 255) / 256, 256>>>(x);

    for (int l = 0; l < LL; l++) {
        init_kernel<<<(NN * HH + 255) / 256, 256>>>();
        wet_kernel <<<(DD * EDD + 255) / 256, 256>>>(We + (size_t)l * EDD * DD);
        wall_prep_kernel<<<(512 * DD + 255) / 256, 256>>>(
            Wq + (size_t)l * DD * DD, Wk + (size_t)l * DD * DD,
            Wv + (size_t)l * DD * DD, Ws + (size_t)l * DD * DD,
            bq + l * DD, bk + l * DD, bv + l * DD, bs + l * DD);

        node_gemm_mma<<<nodeGemmBlocks, 256>>>(q, k, v, ob);

        edge_gemm_mma<<<edgeTiles, 256>>>(be + l * DD);

        gather_kernel<<<NN, 128>>>();

        bn_sum_kernel  <<<256, 128>>>();
        bn_fin_kernel  <<<1, 128>>>(gamma + l * DD, beta + l * DD);
        bn_apply_kernel<<<(NN * DD + 255) / 256, 256>>>(out, (l == LL - 1) ? 1 : 0);
    }
}

// round 13
// speedup vs baseline: 1.5566x; 1.5566x over previous
#include <cuda_runtime.h>
#include <cuda_fp16.h>
#include <cstdint>

// Problem constants (fixed by the reference)
#define NN   50000
#define EE   800000
#define DD   128
#define HH   8
#define CC   16
#define EDD  64
#define LL   3

// ---------------- scratch (static device globals; no allocation) -------------
__device__ __half g_q16[NN * DD];     // q (fp16)
__device__ __half g_k16[NN * DD];     // k (fp16)
__device__ __half g_v16[NN * DD];     // v (fp16)
__device__ float  g_out[NN * DD];     // skip (x@Ws+bs), then final pre-BN out
__device__ __half g_xh [NN * DD];     // x split hi
__device__ __half g_xl [NN * DD];     // x split lo
__device__ __half g_e  [(size_t)EE * DD];      // per-edge e (fp16, CSR order)
__device__ __half g_ea16[(size_t)EE * EDD];    // edge_attr fp16, CSR-permuted
__device__ __half g_wet [DD * EDD];            // We^T fp16 [n=128][k=64]
__device__ __half g_wallh[512 * DD];           // [Wq|Wk|Wv|Ws]^T hi
__device__ __half g_walll[512 * DD];           // lo part
__device__ float  g_ball [512];                // [bq|bk|bv|bs]
__device__ float  g_alpha[(size_t)EE * HH];    // raw scores (CSR order)
__device__ double g_sums[2 * DD];
__device__ float2 g_ab  [DD];
// CSR (dst-sorted edge order; edge_index is launch-constant)
__device__ int    g_deg   [NN];
__device__ int    g_cursor[NN];
__device__ int    g_rowptr[NN + 1];
__device__ int    g_eord  [EE];
__device__ int    g_srcp  [EE];      // src per CSR position
__device__ int    g_dstp  [EE];      // dst per CSR position
__device__ int    g_bsums [256];

// ---------------- helpers ----------------------------------------------------
__device__ __forceinline__ uint32_t smem_u32(const void* p) {
    uint32_t a;
    asm("{ .reg .u64 t; cvta.to.shared.u64 t, %1; cvt.u32.u64 %0, t; }" : "=r"(a) : "l"(p));
    return a;
}
__device__ __forceinline__ uint32_t sw128(uint32_t off) { return off ^ ((off >> 3) & 0x70); }
__device__ __forceinline__ uint32_t sw64 (uint32_t off) { return off ^ ((off >> 3) & 0x30); }

__device__ __forceinline__ void ldmatrix_x4(uint32_t* r, uint32_t addr) {
    asm volatile("ldmatrix.sync.aligned.m8n8.x4.shared.b16 {%0,%1,%2,%3}, [%4];"
                 : "=r"(r[0]), "=r"(r[1]), "=r"(r[2]), "=r"(r[3]) : "r"(addr));
}
__device__ __forceinline__ void mma16816(float* c, const uint32_t* a, const uint32_t* b) {
    asm volatile("mma.sync.aligned.m16n8k16.row.col.f32.f16.f16.f32 "
                 "{%0,%1,%2,%3}, {%4,%5,%6,%7}, {%8,%9}, {%0,%1,%2,%3};"
                 : "+f"(c[0]), "+f"(c[1]), "+f"(c[2]), "+f"(c[3])
                 : "r"(a[0]), "r"(a[1]), "r"(a[2]), "r"(a[3]), "r"(b[0]), "r"(b[1]));
}

// ---------------- CSR build (once per launch) ----------------------------------
__global__ void csr_zero() {
    int i = blockIdx.x * blockDim.x + threadIdx.x;
    if (i < NN) { g_deg[i] = 0; g_cursor[i] = 0; }
}
__global__ void csr_hist(const int* __restrict__ ei) {
    int e = blockIdx.x * blockDim.x + threadIdx.x;
    if (e < EE) atomicAdd(&g_deg[ei[EE + e]], 1);
}
__global__ void csr_scan1() {
    __shared__ int s[256];
    int t = threadIdx.x;
    int i = blockIdx.x * 256 + t;
    int v = (i < NN) ? g_deg[i] : 0;
    s[t] = v;
    __syncthreads();
    for (int st = 1; st < 256; st <<= 1) {
        int x = (t >= st) ? s[t - st] : 0;
        __syncthreads();
        if (t >= st) s[t] += x;
        __syncthreads();
    }
    if (i < NN) g_rowptr[i] = s[t] - v;
    if (t == 255) g_bsums[blockIdx.x] = s[255];
}
__global__ void csr_scan2(int nblocks) {
    __shared__ int s[256];
    int t = threadIdx.x;
    int v = (t < nblocks) ? g_bsums[t] : 0;
    s[t] = v;
    __syncthreads();
    for (int st = 1; st < 256; st <<= 1) {
        int x = (t >= st) ? s[t - st] : 0;
        __syncthreads();
        if (t >= st) s[t] += x;
        __syncthreads();
    }
    if (t < nblocks) g_bsums[t] = s[t] - v;
}
__global__ void csr_scan3() {
    int i = blockIdx.x * blockDim.x + threadIdx.x;
    if (i < NN) g_rowptr[i] += g_bsums[i >> 8];
    if (i == 0) g_rowptr[NN] = EE;
}
__global__ void csr_fill(const int* __restrict__ ei) {
    int e = blockIdx.x * blockDim.x + threadIdx.x;
    if (e >= EE) return;
    int d = ei[EE + e];
    int pos = g_rowptr[d] + atomicAdd(&g_cursor[d], 1);
    g_eord[pos] = e;
}
__global__ void perm_idx_kernel(const int* __restrict__ ei) {
    int p = blockIdx.x * blockDim.x + threadIdx.x;
    if (p >= EE) return;
    int eid = g_eord[p];
    g_srcp[p] = ei[eid];
    g_dstp[p] = ei[EE + eid];
}
__global__ void conv_ea_perm(const float* __restrict__ ea) {
    int i = blockIdx.x * blockDim.x + threadIdx.x;   // over 4-float units
    int p = i >> 4;
    if (p >= EE) return;
    int off = (i & 15) * 4;
    int eid = g_eord[p];
    float4 f = *(const float4*)(ea + (size_t)eid * EDD + off);
    __half2 h01 = __floats2half2_rn(f.x, f.y);
    __half2 h23 = __floats2half2_rn(f.z, f.w);
    uint2 pk;
    pk.x = *(const unsigned*)&h01;
    pk.y = *(const unsigned*)&h23;
    *(uint2*)(g_ea16 + (size_t)p * EDD + off) = pk;
}

// ---------------- one-time / per-layer prep ------------------------------------
__global__ void xsplit0_kernel(const float* __restrict__ x) {
    int i = blockIdx.x * blockDim.x + threadIdx.x;
    if (i >= NN * DD) return;
    float f = x[i];
    __half h = __float2half(f);
    g_xh[i] = h;
    g_xl[i] = __float2half(f - __half2float(h));
}

__global__ void wet_kernel(const float* __restrict__ We) {
    int i = blockIdx.x * blockDim.x + threadIdx.x;
    if (i >= DD * EDD) return;
    int n = i / EDD, k = i % EDD;
    g_wet[i] = __float2half(We[k * DD + n]);
}

__global__ void wall_prep_kernel(const float* __restrict__ Wq, const float* __restrict__ Wk,
                                 const float* __restrict__ Wv, const float* __restrict__ Ws,
                                 const float* __restrict__ bq, const float* __restrict__ bk,
                                 const float* __restrict__ bv, const float* __restrict__ bs) {
    int i = blockIdx.x * blockDim.x + threadIdx.x;
    if (i >= 512 * DD) return;
    int ng = i / DD;
    int k  = i % DD;
    int mtx = ng >> 7, nloc = ng & 127;
    const float* W = (mtx == 0) ? Wq : (mtx == 1) ? Wk : (mtx == 2) ? Wv : Ws;
    float w = W[k * DD + nloc];
    __half h = __float2half(w);
    g_wallh[i] = h;
    g_walll[i] = __float2half(w - __half2float(h));
    if (i < 512) {
        int m2 = i >> 7, l2 = i & 127;
        const float* b = (m2 == 0) ? bq : (m2 == 1) ? bk : (m2 == 2) ? bv : bs;
        g_ball[i] = b[l2];
    }
}

__global__ void init_kernel() {
    int i = threadIdx.x;
    if (i < 2 * DD) g_sums[i] = 0.0;
}

// ------------- fused node GEMM (split-fp16 HMMA): [q|k|v fp16, skip fp32] ------
__global__ void __launch_bounds__(256, 2)
node_gemm_mma(__half* __restrict__ oq, __half* __restrict__ okk,
              __half* __restrict__ ov, float* __restrict__ os) {
    __shared__ __align__(128) __half sAh[128 * 32];
    __shared__ __align__(128) __half sAl[128 * 32];
    __shared__ __align__(128) __half sBh[128 * 32];
    __shared__ __align__(128) __half sBl[128 * 32];
    __shared__ float sbias[128];

    const int tid  = threadIdx.x;
    const int wid  = tid >> 5;
    const int lane = tid & 31;
    const int ntile = blockIdx.x & 3;
    const int mbase = (blockIdx.x >> 2) * 128;

    if (tid < 128) sbias[tid] = g_ball[ntile * 128 + tid];

    float acc[16][4];
#pragma unroll
    for (int i = 0; i < 16; i++)
#pragma unroll
        for (int j = 0; j < 4; j++) acc[i][j] = 0.0f;

    const uint32_t sAhu = smem_u32(sAh);
    const uint32_t sAlu = smem_u32(sAl);
    const uint32_t sBhu = smem_u32(sBh);
    const uint32_t sBlu = smem_u32(sBl);
    const int mrow = wid * 16;

    for (int kc = 0; kc < 4; kc++) {
#pragma unroll
        for (int i = 0; i < 2; i++) {
            int idx = i * 256 + tid;
            int row = idx >> 2, unit = idx & 3;
            int grow = mbase + row;
            uint4 vh = make_uint4(0, 0, 0, 0), vl = make_uint4(0, 0, 0, 0);
            if (grow < NN) {
                size_t g = (size_t)grow * DD + kc * 32 + unit * 8;
                vh = *(const uint4*)(g_xh + g);
                vl = *(const uint4*)(g_xl + g);
            }
            *(uint4*)((char*)sAh + sw64(idx * 16)) = vh;
            *(uint4*)((char*)sAl + sw64(idx * 16)) = vl;
        }
#pragma unroll
        for (int i = 0; i < 2; i++) {
            int idx = i * 256 + tid;
            int row = idx >> 2, unit = idx & 3;
            size_t g = (size_t)(ntile * 128 + row) * DD + kc * 32 + unit * 8;
            *(uint4*)((char*)sBh + sw64(idx * 16)) = *(const uint4*)(g_wallh + g);
            *(uint4*)((char*)sBl + sw64(idx * 16)) = *(const uint4*)(g_walll + g);
        }
        __syncthreads();

#pragma unroll
        for (int t = 0; t < 2; t++) {
            uint32_t ah[4], al[4];
            uint32_t aoff = (uint32_t)(mrow + (lane & 15)) * 64 + t * 32 + ((lane >> 4) * 16);
            ldmatrix_x4(ah, sAhu + sw64(aoff));
            ldmatrix_x4(al, sAlu + sw64(aoff));
#pragma unroll
            for (int np = 0; np < 8; np++) {
                int mtx = lane >> 3;
                uint32_t boff = (uint32_t)(np * 16 + ((mtx >> 1) * 8) + (lane & 7)) * 64
                              + t * 32 + ((mtx & 1) * 16);
                uint32_t bh[4], bl[4];
                ldmatrix_x4(bh, sBhu + sw64(boff));
                ldmatrix_x4(bl, sBlu + sw64(boff));
                mma16816(acc[2 * np],     ah, bh);
                mma16816(acc[2 * np],     ah, bl);
                mma16816(acc[2 * np],     al, bh);
                mma16816(acc[2 * np + 1], ah, bh + 2);
                mma16816(acc[2 * np + 1], ah, bl + 2);
                mma16816(acc[2 * np + 1], al, bh + 2);
            }
        }
        __syncthreads();
    }

    const int r0 = mbase + mrow + (lane >> 2);
    const int cq = (lane & 3) * 2;
    if (ntile == 3) {
#pragma unroll
        for (int nt = 0; nt < 16; nt++) {
            int n = nt * 8 + cq;
            float b0 = sbias[n], b1 = sbias[n + 1];
            if (r0 < NN)
                *(float2*)(os + (size_t)r0 * DD + n) = make_float2(acc[nt][0] + b0, acc[nt][1] + b1);
            if (r0 + 8 < NN)
                *(float2*)(os + (size_t)(r0 + 8) * DD + n) = make_float2(acc[nt][2] + b0, acc[nt][3] + b1);
        }
    } else {
        __half* dst = (ntile == 0) ? oq : (ntile == 1) ? okk : ov;
#pragma unroll
        for (int nt = 0; nt < 16; nt++) {
            int n = nt * 8 + cq;
            float b0 = sbias[n], b1 = sbias[n + 1];
            if (r0 < NN)
                *(__half2*)(dst + (size_t)r0 * DD + n) = __floats2half2_rn(acc[nt][0] + b0, acc[nt][1] + b1);
            if (r0 + 8 < NN)
                *(__half2*)(dst + (size_t)(r0 + 8) * DD + n) = __floats2half2_rn(acc[nt][2] + b0, acc[nt][3] + b1);
        }
    }
}

// -------- edge GEMM (CSR order) + e store + fused alpha -------------------------
__global__ void __launch_bounds__(256, 2)
edge_gemm_mma(const float* __restrict__ bias) {
    __shared__ __align__(128) __half sA[128 * 64];
    __shared__ __align__(128) __half sB[128 * 64];
    __shared__ float sbias[128];

    const int tid  = threadIdx.x;
    const int wid  = tid >> 5;
    const int lane = tid & 31;
    const size_t tile = blockIdx.x;

    if (tid < 128) sbias[tid] = bias[tid];

    const uint4* Ag = (const uint4*)(g_ea16 + tile * 128 * EDD);
#pragma unroll
    for (int i = 0; i < 4; i++) {
        int idx = i * 256 + tid;
        uint4 val = Ag[idx];
        *(uint4*)((char*)sA + sw128(idx * 16)) = val;
    }
    const uint4* Bg = (const uint4*)g_wet;
#pragma unroll
    for (int i = 0; i < 4; i++) {
        int idx = i * 256 + tid;
        uint4 val = Bg[idx];
        *(uint4*)((char*)sB + sw128(idx * 16)) = val;
    }

    // hoist index loads so q/k gathers can issue early in the epilogue
    const int mrow = wid * 16;
    const int p0 = (int)tile * 128 + mrow + (lane >> 2);
    const int p1 = p0 + 8;
    const int src0 = g_srcp[p0], dst0 = g_dstp[p0];
    const int src1 = g_srcp[p1], dst1 = g_dstp[p1];

    __syncthreads();

    const uint32_t sAu = smem_u32(sA);
    const uint32_t sBu = smem_u32(sB);

    uint32_t afrag[4][4];
#pragma unroll
    for (int t = 0; t < 4; t++) {
        uint32_t off = (uint32_t)(mrow + (lane & 15)) * 128 + t * 32 + ((lane >> 4) * 16);
        ldmatrix_x4(afrag[t], sAu + sw128(off));
    }

    float acc[16][4];
#pragma unroll
    for (int i = 0; i < 16; i++)
#pragma unroll
        for (int j = 0; j < 4; j++) acc[i][j] = 0.0f;

#pragma unroll
    for (int t = 0; t < 4; t++) {
#pragma unroll
        for (int np = 0; np < 8; np++) {
            int mtx = lane >> 3;
            int n   = np * 16 + ((mtx >> 1) * 8) + (lane & 7);
            int kb  = t * 32 + ((mtx & 1) * 16);
            uint32_t b[4];
            ldmatrix_x4(b, sBu + sw128((uint32_t)n * 128 + kb));
            mma16816(acc[2 * np],     afrag[t], b);
            mma16816(acc[2 * np + 1], afrag[t], b + 2);
        }
    }

    const int cq = (lane & 3) * 2;
    const __half* q0 = g_q16 + (size_t)dst0 * DD;
    const __half* k0 = g_k16 + (size_t)src0 * DD;
    const __half* q1 = g_q16 + (size_t)dst1 * DD;
    const __half* k1 = g_k16 + (size_t)src1 * DD;
    __half* e0p = g_e + (size_t)p0 * DD;
    __half* e1p = g_e + (size_t)p1 * DD;

    float ps0[8], ps1[8];
#pragma unroll
    for (int h = 0; h < 8; h++) { ps0[h] = 0.0f; ps1[h] = 0.0f; }

#pragma unroll
    for (int nt = 0; nt < 16; nt++) {
        int n = nt * 8 + cq;
        int h = nt >> 1;
        float b0 = sbias[n], b1 = sbias[n + 1];
        float ea0 = acc[nt][0] + b0, ea1 = acc[nt][1] + b1;
        float eb0 = acc[nt][2] + b0, eb1 = acc[nt][3] + b1;
        *(__half2*)(e0p + n) = __floats2half2_rn(ea0, ea1);
        *(__half2*)(e1p + n) = __floats2half2_rn(eb0, eb1);
        float2 qa = __half22float2(*(const __half2*)(q0 + n));
        float2 ka = __half22float2(*(const __half2*)(k0 + n));
        float2 qb = __half22float2(*(const __half2*)(q1 + n));
        float2 kb = __half22float2(*(const __half2*)(k1 + n));
        ps0[h] += qa.x * (ka.x + ea0) + qa.y * (ka.y + ea1);
        ps1[h] += qb.x * (kb.x + eb0) + qb.y * (kb.y + eb1);
    }
#pragma unroll
    for (int h = 0; h < 8; h++) {
        ps0[h] += __shfl_xor_sync(0xFFFFFFFFu, ps0[h], 1);
        ps0[h] += __shfl_xor_sync(0xFFFFFFFFu, ps0[h], 2);
        ps1[h] += __shfl_xor_sync(0xFFFFFFFFu, ps1[h], 1);
        ps1[h] += __shfl_xor_sync(0xFFFFFFFFu, ps1[h], 2);
    }
    const int qid = lane & 3;
#pragma unroll
    for (int h = 0; h < 8; h++) {
        if ((h & 3) == qid) {
            g_alpha[(size_t)p0 * HH + h] = ps0[h] * 0.25f;
            g_alpha[(size_t)p1 * HH + h] = ps1[h] * 0.25f;
        }
    }
}

// ------------- per-node gather: softmax + message sum + skip add ---------------
// alpha/e sequential (CSR order); v gathered (fp16, L2-resident). No atomics.
__global__ void __launch_bounds__(128)
gather_kernel() {
    const int n   = blockIdx.x;
    const int tid = threadIdx.x;
    const int start = g_rowptr[n], end = g_rowptr[n + 1];
    const int i0 = tid >> 3, h8 = tid & 7;
    const int hch = tid >> 4;
    const int lane = tid & 31, w = tid >> 5;

    __shared__ float swmax[4][8];
    __shared__ float samax[8];
    __shared__ float sex[16][8];
    __shared__ int   ssrc[16];
    __shared__ float sden[8];
    __shared__ __align__(16) __half sV[16 * 128];   // 4 KB
    __shared__ __align__(16) __half sE[16 * 128];   // 4 KB

    // max pass with register cache of alpha values (chunks 0..3 cover deg<=64)
    float lmax = -3.0e38f;
    float acache[4];
    {
        int c = 0;
        for (int p = start + i0; p < end; p += 16, c++) {
            float a = g_alpha[(size_t)p * HH + h8];
            if (c < 4) acache[c] = a;
            lmax = fmaxf(lmax, a);
        }
    }
    lmax = fmaxf(lmax, __shfl_xor_sync(0xFFFFFFFFu, lmax, 8));
    lmax = fmaxf(lmax, __shfl_xor_sync(0xFFFFFFFFu, lmax, 16));
    if (lane < 8) swmax[w][lane] = lmax;
    __syncthreads();
    if (tid < 8)
        samax[tid] = fmaxf(fmaxf(swmax[0][tid], swmax[1][tid]),
                           fmaxf(swmax[2][tid], swmax[3][tid]));
    __syncthreads();
    const float amax = samax[h8];

    float msg = 0.0f, den = 0.0f;
    int cc = 0;
    for (int base = start; base < end; base += 16, cc++) {
        int cnt = min(16, end - base);
        if (tid < cnt) ssrc[tid] = g_srcp[base + tid];
        if (i0 < cnt) {
            float a = (cc < 4) ? acache[cc] : g_alpha[(size_t)(base + i0) * HH + h8];
            sex[i0][h8] = __expf(a - amax);
        }
        __syncthreads();   // ssrc ready

        // stage e rows: cnt*16 uint4, fully linear
        {
            const uint4* src = (const uint4*)(g_e + (size_t)base * DD);
            uint4* dst = (uint4*)sE;
            for (int u = tid; u < cnt * 16; u += 128) dst[u] = src[u];
        }
        // stage v rows (fp16): cnt*16 uint4, gathered per row
        {
            uint4* dst = (uint4*)sV;
            for (int u = tid; u < cnt * 16; u += 128) {
                int row = u >> 4, c = u & 15;
                dst[u] = ((const uint4*)(g_v16 + (size_t)ssrc[row] * DD))[c];
            }
        }
        __syncthreads();   // staged data ready

#pragma unroll 4
        for (int i = 0; i < cnt; i++) {
            float ex = sex[i][hch];
            msg += (__half2float(sV[i * 128 + tid]) + __half2float(sE[i * 128 + tid])) * ex;
        }
        if (tid < 8) {
            float s = 0.0f;
            for (int i = 0; i < cnt; i++) s += sex[i][tid];
            den += s;
        }
        __syncthreads();   // protect sex/ssrc for next chunk
    }
    if (tid < 8) sden[tid] = den;
    __syncthreads();

    float o = msg / (sden[hch] + 1e-16f) + g_out[(size_t)n * DD + tid];
    g_out[(size_t)n * DD + tid] = o;
}

// ---- BN column sums (fp64) -----------------------------------------------------
__global__ void bn_sum_kernel() {
    int ch = threadIdx.x;
    double s = 0.0, s2 = 0.0;
    for (int r = blockIdx.x; r < NN; r += gridDim.x) {
        float v = g_out[(size_t)r * DD + ch];
        s  += (double)v;
        s2 += (double)v * (double)v;
    }
    atomicAdd(&g_sums[ch], s);
    atomicAdd(&g_sums[DD + ch], s2);
}

__global__ void bn_fin_kernel(const float* __restrict__ gamma,
                              const float* __restrict__ beta) {
    int ch = threadIdx.x;
    double mu  = g_sums[ch] / (double)NN;
    double var = g_sums[DD + ch] / (double)NN - mu * mu;
    double rs  = 1.0 / sqrt(var + 1e-5);
    float a = gamma[ch] * (float)rs;
    float b = beta[ch] - (float)mu * a;
    g_ab[ch] = make_float2(a, b);
}

__global__ void bn_apply_kernel(float* __restrict__ xo, int write_f32) {
    int idx = blockIdx.x * blockDim.x + threadIdx.x;
    if (idx >= NN * DD) return;
    int ch = idx & (DD - 1);
    float2 c = g_ab[ch];
    float y = g_out[idx] * c.x + c.y;
    y = (y >= 0.0f) ? y : 0.01f * y;
    __half h = __float2half(y);
    g_xh[idx] = h;
    g_xl[idx] = __float2half(y - __half2float(h));
    if (write_f32) xo[idx] = y;
}

// ---------------- driver -------------------------------------------------------
extern "C" void kernel_launch(void* const* d_in, const int* in_sizes, int n_in,
                              void* d_out, int out_size) {
    const float* x     = (const float*)d_in[0];
    const int*   ei    = (const int*)  d_in[1];
    const float* ea    = (const float*)d_in[2];
    const float* Wq    = (const float*)d_in[3];
    const float* bq    = (const float*)d_in[4];
    const float* Wk    = (const float*)d_in[5];
    const float* bk    = (const float*)d_in[6];
    const float* Wv    = (const float*)d_in[7];
    const float* bv    = (const float*)d_in[8];
    const float* We    = (const float*)d_in[9];
    const float* be    = (const float*)d_in[10];
    const float* Ws    = (const float*)d_in[11];
    const float* bs    = (const float*)d_in[12];
    const float* gamma = (const float*)d_in[13];
    const float* beta  = (const float*)d_in[14];
    float* out = (float*)d_out;

    __half *q, *k, *v;
    float *ob;
    cudaGetSymbolAddress((void**)&q,  g_q16);
    cudaGetSymbolAddress((void**)&k,  g_k16);
    cudaGetSymbolAddress((void**)&v,  g_v16);
    cudaGetSymbolAddress((void**)&ob, g_out);

    const int edgeTiles      = EE / 128;                // 6250
    const int nodeGemmBlocks = ((NN + 127) / 128) * 4;  // 1564
    const int nodeB          = (NN + 255) / 256;        // 196

    // one-time per launch: CSR build, permutation, conversions
    csr_zero <<<nodeB, 256>>>();
    csr_hist <<<(EE + 255) / 256, 256>>>(ei);
    csr_scan1<<<nodeB, 256>>>();
    csr_scan2<<<1, 256>>>(nodeB);
    csr_scan3<<<nodeB, 256>>>();
    csr_fill <<<(EE + 255) / 256, 256>>>(ei);
    perm_idx_kernel<<<(EE + 255) / 256, 256>>>(ei);
    conv_ea_perm<<<(int)(((size_t)EE * 16 + 255) / 256), 256>>>(ea);
    xsplit0_kernel<<<(NN * DD + 255) / 256, 256>>>(x);

    for (int l = 0; l < LL; l++) {
        init_kernel<<<1, 256>>>();
        wet_kernel <<<(DD * EDD + 255) / 256, 256>>>(We + (size_t)l * EDD * DD);
        wall_prep_kernel<<<(512 * DD + 255) / 256, 256>>>(
            Wq + (size_t)l * DD * DD, Wk + (size_t)l * DD * DD,
            Wv + (size_t)l * DD * DD, Ws + (size_t)l * DD * DD,
            bq + l * DD, bk + l * DD, bv + l * DD, bs + l * DD);

        node_gemm_mma<<<nodeGemmBlocks, 256>>>(q, k, v, ob);

        edge_gemm_mma<<<edgeTiles, 256>>>(be + l * DD);

        gather_kernel<<<NN, 128>>>();

        bn_sum_kernel  <<<256, 128>>>();
        bn_fin_kernel  <<<1, 128>>>(gamma + l * DD, beta + l * DD);
        bn_apply_kernel<<<(NN * DD + 255) / 256, 256>>>(out, (l == LL - 1) ? 1 : 0);
    }
}

// round 14
// speedup vs baseline: 1.5879x; 1.0201x over previous
#include <cuda_runtime.h>
#include <cuda_fp16.h>
#include <cstdint>

// Problem constants (fixed by the reference)
#define NN   50000
#define EE   800000
#define DD   128
#define HH   8
#define CC   16
#define EDD  64
#define LL   3

// ---------------- scratch (static device globals; no allocation) -------------
__device__ __half g_q16[NN * DD];     // q (fp16)
__device__ __half g_k16[NN * DD];     // k (fp16)
__device__ __half g_v16[NN * DD];     // v (fp16)
__device__ float  g_out [NN * DD];    // pre-BN activations of current layer
__device__ float  g_skip[NN * DD];    // skip (x@Ws+bs)
__device__ __half g_e  [(size_t)EE * DD];      // per-edge e (fp16, CSR order)
__device__ __half g_ea16[(size_t)EE * EDD];    // edge_attr fp16, CSR-permuted
__device__ __half g_wet [DD * EDD];            // We^T fp16 [n=128][k=64]
__device__ __half g_wallh[512 * DD];           // [Wq|Wk|Wv|Ws]^T hi
__device__ __half g_walll[512 * DD];           // lo part
__device__ float  g_ball [512];                // [bq|bk|bv|bs]
__device__ float  g_alpha[(size_t)EE * HH];    // raw scores (CSR order)
__device__ double g_sums[2 * DD];
__device__ float2 g_ab  [DD];
// CSR (dst-sorted edge order; edge_index is launch-constant)
__device__ int    g_deg   [NN];
__device__ int    g_cursor[NN];
__device__ int    g_rowptr[NN + 1];
__device__ int    g_eord  [EE];
__device__ int    g_srcp  [EE];      // src per CSR position
__device__ int    g_dstp  [EE];      // dst per CSR position
__device__ int    g_bsums [256];

// ---------------- helpers ----------------------------------------------------
__device__ __forceinline__ uint32_t smem_u32(const void* p) {
    uint32_t a;
    asm("{ .reg .u64 t; cvta.to.shared.u64 t, %1; cvt.u32.u64 %0, t; }" : "=r"(a) : "l"(p));
    return a;
}
__device__ __forceinline__ uint32_t sw128(uint32_t off) { return off ^ ((off >> 3) & 0x70); }
__device__ __forceinline__ uint32_t sw64 (uint32_t off) { return off ^ ((off >> 3) & 0x30); }
__device__ __forceinline__ uint32_t pack2(__half a, __half b) {
    __half2 t = __halves2half2(a, b);
    return *(const uint32_t*)&t;
}

__device__ __forceinline__ void ldmatrix_x4(uint32_t* r, uint32_t addr) {
    asm volatile("ldmatrix.sync.aligned.m8n8.x4.shared.b16 {%0,%1,%2,%3}, [%4];"
                 : "=r"(r[0]), "=r"(r[1]), "=r"(r[2]), "=r"(r[3]) : "r"(addr));
}
__device__ __forceinline__ void mma16816(float* c, const uint32_t* a, const uint32_t* b) {
    asm volatile("mma.sync.aligned.m16n8k16.row.col.f32.f16.f16.f32 "
                 "{%0,%1,%2,%3}, {%4,%5,%6,%7}, {%8,%9}, {%0,%1,%2,%3};"
                 : "+f"(c[0]), "+f"(c[1]), "+f"(c[2]), "+f"(c[3])
                 : "r"(a[0]), "r"(a[1]), "r"(a[2]), "r"(a[3]), "r"(b[0]), "r"(b[1]));
}

// ---------------- CSR build (once per launch) ----------------------------------
__global__ void csr_zero() {
    int i = blockIdx.x * blockDim.x + threadIdx.x;
    if (i < NN) { g_deg[i] = 0; g_cursor[i] = 0; }
}
__global__ void csr_hist(const int* __restrict__ ei) {
    int e = blockIdx.x * blockDim.x + threadIdx.x;
    if (e < EE) atomicAdd(&g_deg[ei[EE + e]], 1);
}
__global__ void csr_scan1() {
    __shared__ int s[256];
    int t = threadIdx.x;
    int i = blockIdx.x * 256 + t;
    int v = (i < NN) ? g_deg[i] : 0;
    s[t] = v;
    __syncthreads();
    for (int st = 1; st < 256; st <<= 1) {
        int x = (t >= st) ? s[t - st] : 0;
        __syncthreads();
        if (t >= st) s[t] += x;
        __syncthreads();
    }
    if (i < NN) g_rowptr[i] = s[t] - v;
    if (t == 255) g_bsums[blockIdx.x] = s[255];
}
__global__ void csr_scan2(int nblocks) {
    __shared__ int s[256];
    int t = threadIdx.x;
    int v = (t < nblocks) ? g_bsums[t] : 0;
    s[t] = v;
    __syncthreads();
    for (int st = 1; st < 256; st <<= 1) {
        int x = (t >= st) ? s[t - st] : 0;
        __syncthreads();
        if (t >= st) s[t] += x;
        __syncthreads();
    }
    if (t < nblocks) g_bsums[t] = s[t] - v;
}
__global__ void csr_scan3() {
    int i = blockIdx.x * blockDim.x + threadIdx.x;
    if (i < NN) g_rowptr[i] += g_bsums[i >> 8];
    if (i == 0) g_rowptr[NN] = EE;
}
__global__ void csr_fill(const int* __restrict__ ei) {
    int e = blockIdx.x * blockDim.x + threadIdx.x;
    if (e >= EE) return;
    int d = ei[EE + e];
    int pos = g_rowptr[d] + atomicAdd(&g_cursor[d], 1);
    g_eord[pos] = e;
}
__global__ void perm_idx_kernel(const int* __restrict__ ei) {
    int p = blockIdx.x * blockDim.x + threadIdx.x;
    if (p >= EE) return;
    int eid = g_eord[p];
    g_srcp[p] = ei[eid];
    g_dstp[p] = ei[EE + eid];
}
__global__ void conv_ea_perm(const float* __restrict__ ea) {
    int i = blockIdx.x * blockDim.x + threadIdx.x;   // over 4-float units
    int p = i >> 4;
    if (p >= EE) return;
    int off = (i & 15) * 4;
    int eid = g_eord[p];
    float4 f = *(const float4*)(ea + (size_t)eid * EDD + off);
    __half2 h01 = __floats2half2_rn(f.x, f.y);
    __half2 h23 = __floats2half2_rn(f.z, f.w);
    uint2 pk;
    pk.x = *(const unsigned*)&h01;
    pk.y = *(const unsigned*)&h23;
    *(uint2*)(g_ea16 + (size_t)p * EDD + off) = pk;
}

// ---------------- merged per-layer prep: sums init + We^T + Wall ----------------
__global__ void prep_kernel(const float* __restrict__ We,
                            const float* __restrict__ Wq, const float* __restrict__ Wk,
                            const float* __restrict__ Wv, const float* __restrict__ Ws,
                            const float* __restrict__ bq, const float* __restrict__ bk,
                            const float* __restrict__ bv, const float* __restrict__ bs) {
    int i = blockIdx.x * blockDim.x + threadIdx.x;
    if (i < 2 * DD) g_sums[i] = 0.0;
    if (i < DD * EDD) {
        int n = i / EDD, k = i % EDD;
        g_wet[i] = __float2half(We[k * DD + n]);
    }
    if (i < 512 * DD) {
        int ng = i / DD;
        int k  = i % DD;
        int mtx = ng >> 7, nloc = ng & 127;
        const float* W = (mtx == 0) ? Wq : (mtx == 1) ? Wk : (mtx == 2) ? Wv : Ws;
        float w = W[k * DD + nloc];
        __half h = __float2half(w);
        g_wallh[i] = h;
        g_walll[i] = __float2half(w - __half2float(h));
        if (i < 512) {
            int m2 = i >> 7, l2 = i & 127;
            const float* b = (m2 == 0) ? bq : (m2 == 1) ? bk : (m2 == 2) ? bv : bs;
            g_ball[i] = b[l2];
        }
    }
}

// ------------- fused node GEMM: BN affine + LeakyReLU + split during A load ----
// A is fp32 (x for layer 0, pre-BN g_out afterwards). act=1 applies g_ab + leaky.
__global__ void __launch_bounds__(256, 2)
node_gemm_mma(const float* __restrict__ A, int act,
              __half* __restrict__ oq, __half* __restrict__ okk,
              __half* __restrict__ ov, float* __restrict__ os) {
    __shared__ __align__(128) __half sAh[128 * 32];
    __shared__ __align__(128) __half sAl[128 * 32];
    __shared__ __align__(128) __half sBh[128 * 32];
    __shared__ __align__(128) __half sBl[128 * 32];
    __shared__ float sbias[128];
    __shared__ float2 sab[128];

    const int tid  = threadIdx.x;
    const int wid  = tid >> 5;
    const int lane = tid & 31;
    const int ntile = blockIdx.x & 3;
    const int mbase = (blockIdx.x >> 2) * 128;

    if (tid < 128) {
        sbias[tid] = g_ball[ntile * 128 + tid];
        sab[tid]   = act ? g_ab[tid] : make_float2(1.0f, 0.0f);
    }
    __syncthreads();

    float acc[16][4];
#pragma unroll
    for (int i = 0; i < 16; i++)
#pragma unroll
        for (int j = 0; j < 4; j++) acc[i][j] = 0.0f;

    const uint32_t sAhu = smem_u32(sAh);
    const uint32_t sAlu = smem_u32(sAl);
    const uint32_t sBhu = smem_u32(sBh);
    const uint32_t sBlu = smem_u32(sBl);
    const int mrow = wid * 16;

    for (int kc = 0; kc < 4; kc++) {
#pragma unroll
        for (int i = 0; i < 2; i++) {
            int idx = i * 256 + tid;
            int row = idx >> 2, unit = idx & 3;
            int grow = mbase + row;
            uint4 vh = make_uint4(0, 0, 0, 0), vl = make_uint4(0, 0, 0, 0);
            if (grow < NN) {
                const float* ap = A + (size_t)grow * DD + kc * 32 + unit * 8;
                float4 f0 = *(const float4*)ap;
                float4 f1 = *(const float4*)(ap + 4);
                float y[8] = {f0.x, f0.y, f0.z, f0.w, f1.x, f1.y, f1.z, f1.w};
                int ch0 = kc * 32 + unit * 8;
                __half hh[8], hl[8];
#pragma unroll
                for (int j = 0; j < 8; j++) {
                    float f = y[j];
                    if (act) {
                        float2 c = sab[ch0 + j];
                        f = f * c.x + c.y;
                        f = (f >= 0.0f) ? f : 0.01f * f;
                    }
                    __half h = __float2half(f);
                    hh[j] = h;
                    hl[j] = __float2half(f - __half2float(h));
                }
                vh = make_uint4(pack2(hh[0], hh[1]), pack2(hh[2], hh[3]),
                                pack2(hh[4], hh[5]), pack2(hh[6], hh[7]));
                vl = make_uint4(pack2(hl[0], hl[1]), pack2(hl[2], hl[3]),
                                pack2(hl[4], hl[5]), pack2(hl[6], hl[7]));
            }
            *(uint4*)((char*)sAh + sw64(idx * 16)) = vh;
            *(uint4*)((char*)sAl + sw64(idx * 16)) = vl;
        }
#pragma unroll
        for (int i = 0; i < 2; i++) {
            int idx = i * 256 + tid;
            int row = idx >> 2, unit = idx & 3;
            size_t g = (size_t)(ntile * 128 + row) * DD + kc * 32 + unit * 8;
            *(uint4*)((char*)sBh + sw64(idx * 16)) = *(const uint4*)(g_wallh + g);
            *(uint4*)((char*)sBl + sw64(idx * 16)) = *(const uint4*)(g_walll + g);
        }
        __syncthreads();

#pragma unroll
        for (int t = 0; t < 2; t++) {
            uint32_t ah[4], al[4];
            uint32_t aoff = (uint32_t)(mrow + (lane & 15)) * 64 + t * 32 + ((lane >> 4) * 16);
            ldmatrix_x4(ah, sAhu + sw64(aoff));
            ldmatrix_x4(al, sAlu + sw64(aoff));
#pragma unroll
            for (int np = 0; np < 8; np++) {
                int mtx = lane >> 3;
                uint32_t boff = (uint32_t)(np * 16 + ((mtx >> 1) * 8) + (lane & 7)) * 64
                              + t * 32 + ((mtx & 1) * 16);
                uint32_t bh[4], bl[4];
                ldmatrix_x4(bh, sBhu + sw64(boff));
                ldmatrix_x4(bl, sBlu + sw64(boff));
                mma16816(acc[2 * np],     ah, bh);
                mma16816(acc[2 * np],     ah, bl);
                mma16816(acc[2 * np],     al, bh);
                mma16816(acc[2 * np + 1], ah, bh + 2);
                mma16816(acc[2 * np + 1], ah, bl + 2);
                mma16816(acc[2 * np + 1], al, bh + 2);
            }
        }
        __syncthreads();
    }

    const int r0 = mbase + mrow + (lane >> 2);
    const int cq = (lane & 3) * 2;
    if (ntile == 3) {
#pragma unroll
        for (int nt = 0; nt < 16; nt++) {
            int n = nt * 8 + cq;
            float b0 = sbias[n], b1 = sbias[n + 1];
            if (r0 < NN)
                *(float2*)(os + (size_t)r0 * DD + n) = make_float2(acc[nt][0] + b0, acc[nt][1] + b1);
            if (r0 + 8 < NN)
                *(float2*)(os + (size_t)(r0 + 8) * DD + n) = make_float2(acc[nt][2] + b0, acc[nt][3] + b1);
        }
    } else {
        __half* dst = (ntile == 0) ? oq : (ntile == 1) ? okk : ov;
#pragma unroll
        for (int nt = 0; nt < 16; nt++) {
            int n = nt * 8 + cq;
            float b0 = sbias[n], b1 = sbias[n + 1];
            if (r0 < NN)
                *(__half2*)(dst + (size_t)r0 * DD + n) = __floats2half2_rn(acc[nt][0] + b0, acc[nt][1] + b1);
            if (r0 + 8 < NN)
                *(__half2*)(dst + (size_t)(r0 + 8) * DD + n) = __floats2half2_rn(acc[nt][2] + b0, acc[nt][3] + b1);
        }
    }
}

// -------- edge GEMM (CSR order) + e store + fused alpha -------------------------
__global__ void __launch_bounds__(256, 2)
edge_gemm_mma(const float* __restrict__ bias) {
    __shared__ __align__(128) __half sA[128 * 64];
    __shared__ __align__(128) __half sB[128 * 64];
    __shared__ float sbias[128];

    const int tid  = threadIdx.x;
    const int wid  = tid >> 5;
    const int lane = tid & 31;
    const size_t tile = blockIdx.x;

    if (tid < 128) sbias[tid] = bias[tid];

    const uint4* Ag = (const uint4*)(g_ea16 + tile * 128 * EDD);
#pragma unroll
    for (int i = 0; i < 4; i++) {
        int idx = i * 256 + tid;
        uint4 val = Ag[idx];
        *(uint4*)((char*)sA + sw128(idx * 16)) = val;
    }
    const uint4* Bg = (const uint4*)g_wet;
#pragma unroll
    for (int i = 0; i < 4; i++) {
        int idx = i * 256 + tid;
        uint4 val = Bg[idx];
        *(uint4*)((char*)sB + sw128(idx * 16)) = val;
    }

    const int mrow = wid * 16;
    const int p0 = (int)tile * 128 + mrow + (lane >> 2);
    const int p1 = p0 + 8;
    const int src0 = g_srcp[p0], dst0 = g_dstp[p0];
    const int src1 = g_srcp[p1], dst1 = g_dstp[p1];

    __syncthreads();

    const uint32_t sAu = smem_u32(sA);
    const uint32_t sBu = smem_u32(sB);

    uint32_t afrag[4][4];
#pragma unroll
    for (int t = 0; t < 4; t++) {
        uint32_t off = (uint32_t)(mrow + (lane & 15)) * 128 + t * 32 + ((lane >> 4) * 16);
        ldmatrix_x4(afrag[t], sAu + sw128(off));
    }

    float acc[16][4];
#pragma unroll
    for (int i = 0; i < 16; i++)
#pragma unroll
        for (int j = 0; j < 4; j++) acc[i][j] = 0.0f;

#pragma unroll
    for (int t = 0; t < 4; t++) {
#pragma unroll
        for (int np = 0; np < 8; np++) {
            int mtx = lane >> 3;
            int n   = np * 16 + ((mtx >> 1) * 8) + (lane & 7);
            int kb  = t * 32 + ((mtx & 1) * 16);
            uint32_t b[4];
            ldmatrix_x4(b, sBu + sw128((uint32_t)n * 128 + kb));
            mma16816(acc[2 * np],     afrag[t], b);
            mma16816(acc[2 * np + 1], afrag[t], b + 2);
        }
    }

    const int cq = (lane & 3) * 2;
    const __half* q0 = g_q16 + (size_t)dst0 * DD;
    const __half* k0 = g_k16 + (size_t)src0 * DD;
    const __half* q1 = g_q16 + (size_t)dst1 * DD;
    const __half* k1 = g_k16 + (size_t)src1 * DD;
    __half* e0p = g_e + (size_t)p0 * DD;
    __half* e1p = g_e + (size_t)p1 * DD;

    float ps0[8], ps1[8];
#pragma unroll
    for (int h = 0; h < 8; h++) { ps0[h] = 0.0f; ps1[h] = 0.0f; }

#pragma unroll
    for (int nt = 0; nt < 16; nt++) {
        int n = nt * 8 + cq;
        int h = nt >> 1;
        float b0 = sbias[n], b1 = sbias[n + 1];
        float ea0 = acc[nt][0] + b0, ea1 = acc[nt][1] + b1;
        float eb0 = acc[nt][2] + b0, eb1 = acc[nt][3] + b1;
        *(__half2*)(e0p + n) = __floats2half2_rn(ea0, ea1);
        *(__half2*)(e1p + n) = __floats2half2_rn(eb0, eb1);
        float2 qa = __half22float2(*(const __half2*)(q0 + n));
        float2 ka = __half22float2(*(const __half2*)(k0 + n));
        float2 qb = __half22float2(*(const __half2*)(q1 + n));
        float2 kb = __half22float2(*(const __half2*)(k1 + n));
        ps0[h] += qa.x * (ka.x + ea0) + qa.y * (ka.y + ea1);
        ps1[h] += qb.x * (kb.x + eb0) + qb.y * (kb.y + eb1);
    }
#pragma unroll
    for (int h = 0; h < 8; h++) {
        ps0[h] += __shfl_xor_sync(0xFFFFFFFFu, ps0[h], 1);
        ps0[h] += __shfl_xor_sync(0xFFFFFFFFu, ps0[h], 2);
        ps1[h] += __shfl_xor_sync(0xFFFFFFFFu, ps1[h], 1);
        ps1[h] += __shfl_xor_sync(0xFFFFFFFFu, ps1[h], 2);
    }
    const int qid = lane & 3;
#pragma unroll
    for (int h = 0; h < 8; h++) {
        if ((h & 3) == qid) {
            g_alpha[(size_t)p0 * HH + h] = ps0[h] * 0.25f;
            g_alpha[(size_t)p1 * HH + h] = ps1[h] * 0.25f;
        }
    }
}

// ------------- per-node gather: softmax + message sum + skip add ---------------
__global__ void __launch_bounds__(128)
gather_kernel() {
    const int n   = blockIdx.x;
    const int tid = threadIdx.x;
    const int start = g_rowptr[n], end = g_rowptr[n + 1];
    const int i0 = tid >> 3, h8 = tid & 7;
    const int hch = tid >> 4;
    const int lane = tid & 31, w = tid >> 5;

    __shared__ float swmax[4][8];
    __shared__ float samax[8];
    __shared__ float sex[16][8];
    __shared__ int   ssrc[16];
    __shared__ float sden[8];
    __shared__ __align__(16) __half sV[16 * 128];   // 4 KB
    __shared__ __align__(16) __half sE[16 * 128];   // 4 KB

    // max pass with register cache of alpha values (chunks 0..3 cover deg<=64)
    float lmax = -3.0e38f;
    float acache[4];
    {
        int c = 0;
        for (int p = start + i0; p < end; p += 16, c++) {
            float a = g_alpha[(size_t)p * HH + h8];
            if (c < 4) acache[c] = a;
            lmax = fmaxf(lmax, a);
        }
    }
    lmax = fmaxf(lmax, __shfl_xor_sync(0xFFFFFFFFu, lmax, 8));
    lmax = fmaxf(lmax, __shfl_xor_sync(0xFFFFFFFFu, lmax, 16));
    if (lane < 8) swmax[w][lane] = lmax;
    __syncthreads();
    if (tid < 8)
        samax[tid] = fmaxf(fmaxf(swmax[0][tid], swmax[1][tid]),
                           fmaxf(swmax[2][tid], swmax[3][tid]));
    __syncthreads();
    const float amax = samax[h8];

    float msg = 0.0f, den = 0.0f;
    int cc = 0;
    for (int base = start; base < end; base += 16, cc++) {
        int cnt = min(16, end - base);
        if (tid < cnt) ssrc[tid] = g_srcp[base + tid];
        if (i0 < cnt) {
            float a = (cc < 4) ? acache[cc] : g_alpha[(size_t)(base + i0) * HH + h8];
            sex[i0][h8] = __expf(a - amax);
        }
        __syncthreads();

        {
            const uint4* src = (const uint4*)(g_e + (size_t)base * DD);
            uint4* dst = (uint4*)sE;
            for (int u = tid; u < cnt * 16; u += 128) dst[u] = src[u];
        }
        {
            uint4* dst = (uint4*)sV;
            for (int u = tid; u < cnt * 16; u += 128) {
                int row = u >> 4, c = u & 15;
                dst[u] = ((const uint4*)(g_v16 + (size_t)ssrc[row] * DD))[c];
            }
        }
        __syncthreads();

#pragma unroll 4
        for (int i = 0; i < cnt; i++) {
            float ex = sex[i][hch];
            msg += (__half2float(sV[i * 128 + tid]) + __half2float(sE[i * 128 + tid])) * ex;
        }
        if (tid < 8) {
            float s = 0.0f;
            for (int i = 0; i < cnt; i++) s += sex[i][tid];
            den += s;
        }
        __syncthreads();
    }
    if (tid < 8) sden[tid] = den;
    __syncthreads();

    float o = msg / (sden[hch] + 1e-16f) + g_skip[(size_t)n * DD + tid];
    g_out[(size_t)n * DD + tid] = o;
}

// ---- BN column sums (fp64) -----------------------------------------------------
__global__ void bn_sum_kernel() {
    int ch = threadIdx.x;
    double s = 0.0, s2 = 0.0;
    for (int r = blockIdx.x; r < NN; r += gridDim.x) {
        float v = g_out[(size_t)r * DD + ch];
        s  += (double)v;
        s2 += (double)v * (double)v;
    }
    atomicAdd(&g_sums[ch], s);
    atomicAdd(&g_sums[DD + ch], s2);
}

__global__ void bn_fin_kernel(const float* __restrict__ gamma,
                              const float* __restrict__ beta) {
    int ch = threadIdx.x;
    double mu  = g_sums[ch] / (double)NN;
    double var = g_sums[DD + ch] / (double)NN - mu * mu;
    double rs  = 1.0 / sqrt(var + 1e-5);
    float a = gamma[ch] * (float)rs;
    float b = beta[ch] - (float)mu * a;
    g_ab[ch] = make_float2(a, b);
}

// final BN apply + LeakyReLU -> harness output
__global__ void bn_apply_final(float* __restrict__ xo) {
    int idx = blockIdx.x * blockDim.x + threadIdx.x;
    if (idx >= NN * DD) return;
    int ch = idx & (DD - 1);
    float2 c = g_ab[ch];
    float y = g_out[idx] * c.x + c.y;
    xo[idx] = (y >= 0.0f) ? y : 0.01f * y;
}

// ---------------- driver -------------------------------------------------------
extern "C" void kernel_launch(void* const* d_in, const int* in_sizes, int n_in,
                              void* d_out, int out_size) {
    const float* x     = (const float*)d_in[0];
    const int*   ei    = (const int*)  d_in[1];
    const float* ea    = (const float*)d_in[2];
    const float* Wq    = (const float*)d_in[3];
    const float* bq    = (const float*)d_in[4];
    const float* Wk    = (const float*)d_in[5];
    const float* bk    = (const float*)d_in[6];
    const float* Wv    = (const float*)d_in[7];
    const float* bv    = (const float*)d_in[8];
    const float* We    = (const float*)d_in[9];
    const float* be    = (const float*)d_in[10];
    const float* Ws    = (const float*)d_in[11];
    const float* bs    = (const float*)d_in[12];
    const float* gamma = (const float*)d_in[13];
    const float* beta  = (const float*)d_in[14];
    float* out = (float*)d_out;

    __half *q, *k, *v;
    float *ob, *sk;
    cudaGetSymbolAddress((void**)&q,  g_q16);
    cudaGetSymbolAddress((void**)&k,  g_k16);
    cudaGetSymbolAddress((void**)&v,  g_v16);
    cudaGetSymbolAddress((void**)&ob, g_out);
    cudaGetSymbolAddress((void**)&sk, g_skip);

    const int edgeTiles      = EE / 128;                // 6250
    const int nodeGemmBlocks = ((NN + 127) / 128) * 4;  // 1564
    const int nodeB          = (NN + 255) / 256;        // 196
    const int prepBlocks     = (512 * DD + 255) / 256;  // 256

    // one-time per launch: CSR build, permutation, conversions
    csr_zero <<<nodeB, 256>>>();
    csr_hist <<<(EE + 255) / 256, 256>>>(ei);
    csr_scan1<<<nodeB, 256>>>();
    csr_scan2<<<1, 256>>>(nodeB);
    csr_scan3<<<nodeB, 256>>>();
    csr_fill <<<(EE + 255) / 256, 256>>>(ei);
    perm_idx_kernel<<<(EE + 255) / 256, 256>>>(ei);
    conv_ea_perm<<<(int)(((size_t)EE * 16 + 255) / 256), 256>>>(ea);

    for (int l = 0; l < LL; l++) {
        prep_kernel<<<prepBlocks, 256>>>(
            We + (size_t)l * EDD * DD,
            Wq + (size_t)l * DD * DD, Wk + (size_t)l * DD * DD,
            Wv + (size_t)l * DD * DD, Ws + (size_t)l * DD * DD,
            bq + l * DD, bk + l * DD, bv + l * DD, bs + l * DD);

        node_gemm_mma<<<nodeGemmBlocks, 256>>>((l == 0) ? x : ob, (l > 0) ? 1 : 0,
                                               q, k, v, sk);

        edge_gemm_mma<<<edgeTiles, 256>>>(be + l * DD);

        gather_kernel<<<NN, 128>>>();

        bn_sum_kernel<<<256, 128>>>();
        bn_fin_kernel<<<1, 128>>>(gamma + l * DD, beta + l * DD);
    }
    bn_apply_final<<<(NN * DD + 255) / 256, 256>>>(out);
}

// round 15
// speedup vs baseline: 1.8469x; 1.1631x over previous
#include <cuda_runtime.h>
#include <cuda_fp16.h>
#include <cstdint>

// Problem constants (fixed by the reference)
#define NN   50000
#define EE   800000
#define DD   128
#define HH   8
#define CC   16
#define EDD  64
#define LL   3

// ---------------- scratch (static device globals; no allocation) -------------
__device__ __half g_q16[NN * DD];     // q (fp16)
__device__ __half g_k16[NN * DD];     // k (fp16)
__device__ __half g_v16[NN * DD];     // v (fp16)
__device__ float  g_out [NN * DD];    // pre-BN activations of current layer
__device__ float  g_skip[NN * DD];    // skip (x@Ws+bs)
__device__ __half g_e  [(size_t)EE * DD];      // per-edge e (fp16, CSR order)
__device__ __half g_ea16[(size_t)EE * EDD];    // edge_attr fp16, CSR-permuted
__device__ __half g_wet [DD * EDD];            // We^T fp16 [n=128][k=64]
__device__ __half g_wallh[512 * DD];           // [Wq|Wk|Wv|Ws]^T hi
__device__ __half g_walll[512 * DD];           // lo part
__device__ float  g_ball [512];                // [bq|bk|bv|bs]
__device__ float  g_alpha[(size_t)EE * HH];    // raw scores (CSR order)
__device__ double g_sums[2 * DD];
__device__ float2 g_ab  [DD];
// CSR (dst-sorted edge order; edge_index is launch-constant)
__device__ int    g_deg   [NN];
__device__ int    g_cursor[NN];
__device__ int    g_rowptr[NN + 1];
__device__ int    g_eord  [EE];
__device__ int    g_srcp  [EE];      // src per CSR position
__device__ int    g_dstp  [EE];      // dst per CSR position
__device__ int    g_bsums [256];

// ---------------- helpers ----------------------------------------------------
__device__ __forceinline__ uint32_t smem_u32(const void* p) {
    uint32_t a;
    asm("{ .reg .u64 t; cvta.to.shared.u64 t, %1; cvt.u32.u64 %0, t; }" : "=r"(a) : "l"(p));
    return a;
}
__device__ __forceinline__ uint32_t sw128(uint32_t off) { return off ^ ((off >> 3) & 0x70); }
__device__ __forceinline__ uint32_t sw64 (uint32_t off) { return off ^ ((off >> 3) & 0x30); }
__device__ __forceinline__ uint32_t pack2(__half a, __half b) {
    __half2 t = __halves2half2(a, b);
    return *(const uint32_t*)&t;
}

__device__ __forceinline__ void ldmatrix_x4(uint32_t* r, uint32_t addr) {
    asm volatile("ldmatrix.sync.aligned.m8n8.x4.shared.b16 {%0,%1,%2,%3}, [%4];"
                 : "=r"(r[0]), "=r"(r[1]), "=r"(r[2]), "=r"(r[3]) : "r"(addr));
}
__device__ __forceinline__ void mma16816(float* c, const uint32_t* a, const uint32_t* b) {
    asm volatile("mma.sync.aligned.m16n8k16.row.col.f32.f16.f16.f32 "
                 "{%0,%1,%2,%3}, {%4,%5,%6,%7}, {%8,%9}, {%0,%1,%2,%3};"
                 : "+f"(c[0]), "+f"(c[1]), "+f"(c[2]), "+f"(c[3])
                 : "r"(a[0]), "r"(a[1]), "r"(a[2]), "r"(a[3]), "r"(b[0]), "r"(b[1]));
}

// ---------------- CSR build (once per launch) ----------------------------------
__global__ void csr_zero() {
    int i = blockIdx.x * blockDim.x + threadIdx.x;
    if (i < NN) { g_deg[i] = 0; g_cursor[i] = 0; }
}
__global__ void csr_hist(const int* __restrict__ ei) {
    int e = blockIdx.x * blockDim.x + threadIdx.x;
    if (e < EE) atomicAdd(&g_deg[ei[EE + e]], 1);
}
__global__ void csr_scan1() {
    __shared__ int s[256];
    int t = threadIdx.x;
    int i = blockIdx.x * 256 + t;
    int v = (i < NN) ? g_deg[i] : 0;
    s[t] = v;
    __syncthreads();
    for (int st = 1; st < 256; st <<= 1) {
        int x = (t >= st) ? s[t - st] : 0;
        __syncthreads();
        if (t >= st) s[t] += x;
        __syncthreads();
    }
    if (i < NN) g_rowptr[i] = s[t] - v;
    if (t == 255) g_bsums[blockIdx.x] = s[255];
}
__global__ void csr_scan2(int nblocks) {
    __shared__ int s[256];
    int t = threadIdx.x;
    int v = (t < nblocks) ? g_bsums[t] : 0;
    s[t] = v;
    __syncthreads();
    for (int st = 1; st < 256; st <<= 1) {
        int x = (t >= st) ? s[t - st] : 0;
        __syncthreads();
        if (t >= st) s[t] += x;
        __syncthreads();
    }
    if (t < nblocks) g_bsums[t] = s[t] - v;
}
__global__ void csr_scan3() {
    int i = blockIdx.x * blockDim.x + threadIdx.x;
    if (i < NN) g_rowptr[i] += g_bsums[i >> 8];
    if (i == 0) g_rowptr[NN] = EE;
}
__global__ void csr_fill(const int* __restrict__ ei) {
    int e = blockIdx.x * blockDim.x + threadIdx.x;
    if (e >= EE) return;
    int d = ei[EE + e];
    int pos = g_rowptr[d] + atomicAdd(&g_cursor[d], 1);
    g_eord[pos] = e;
}
__global__ void perm_idx_kernel(const int* __restrict__ ei) {
    int p = blockIdx.x * blockDim.x + threadIdx.x;
    if (p >= EE) return;
    int eid = g_eord[p];
    g_srcp[p] = ei[eid];
    g_dstp[p] = ei[EE + eid];
}
__global__ void conv_ea_perm(const float* __restrict__ ea) {
    int i = blockIdx.x * blockDim.x + threadIdx.x;   // over 4-float units
    int p = i >> 4;
    if (p >= EE) return;
    int off = (i & 15) * 4;
    int eid = g_eord[p];
    float4 f = *(const float4*)(ea + (size_t)eid * EDD + off);
    __half2 h01 = __floats2half2_rn(f.x, f.y);
    __half2 h23 = __floats2half2_rn(f.z, f.w);
    uint2 pk;
    pk.x = *(const unsigned*)&h01;
    pk.y = *(const unsigned*)&h23;
    *(uint2*)(g_ea16 + (size_t)p * EDD + off) = pk;
}

// ---------------- merged per-layer prep: sums init + We^T + Wall ----------------
__global__ void prep_kernel(const float* __restrict__ We,
                            const float* __restrict__ Wq, const float* __restrict__ Wk,
                            const float* __restrict__ Wv, const float* __restrict__ Ws,
                            const float* __restrict__ bq, const float* __restrict__ bk,
                            const float* __restrict__ bv, const float* __restrict__ bs) {
    int i = blockIdx.x * blockDim.x + threadIdx.x;
    if (i < 2 * DD) g_sums[i] = 0.0;
    if (i < DD * EDD) {
        int n = i / EDD, k = i % EDD;
        g_wet[i] = __float2half(We[k * DD + n]);
    }
    if (i < 512 * DD) {
        int ng = i / DD;
        int k  = i % DD;
        int mtx = ng >> 7, nloc = ng & 127;
        const float* W = (mtx == 0) ? Wq : (mtx == 1) ? Wk : (mtx == 2) ? Wv : Ws;
        float w = W[k * DD + nloc];
        __half h = __float2half(w);
        g_wallh[i] = h;
        g_walll[i] = __float2half(w - __half2float(h));
        if (i < 512) {
            int m2 = i >> 7, l2 = i & 127;
            const float* b = (m2 == 0) ? bq : (m2 == 1) ? bk : (m2 == 2) ? bv : bs;
            g_ball[i] = b[l2];
        }
    }
}

// ------------- fused node GEMM: BN affine + LeakyReLU + split during A load ----
__global__ void __launch_bounds__(256, 2)
node_gemm_mma(const float* __restrict__ A, int act,
              __half* __restrict__ oq, __half* __restrict__ okk,
              __half* __restrict__ ov, float* __restrict__ os) {
    __shared__ __align__(128) __half sAh[128 * 32];
    __shared__ __align__(128) __half sAl[128 * 32];
    __shared__ __align__(128) __half sBh[128 * 32];
    __shared__ __align__(128) __half sBl[128 * 32];
    __shared__ float sbias[128];
    __shared__ float2 sab[128];

    const int tid  = threadIdx.x;
    const int wid  = tid >> 5;
    const int lane = tid & 31;
    const int ntile = blockIdx.x & 3;
    const int mbase = (blockIdx.x >> 2) * 128;

    if (tid < 128) {
        sbias[tid] = g_ball[ntile * 128 + tid];
        sab[tid]   = act ? g_ab[tid] : make_float2(1.0f, 0.0f);
    }
    __syncthreads();

    float acc[16][4];
#pragma unroll
    for (int i = 0; i < 16; i++)
#pragma unroll
        for (int j = 0; j < 4; j++) acc[i][j] = 0.0f;

    const uint32_t sAhu = smem_u32(sAh);
    const uint32_t sAlu = smem_u32(sAl);
    const uint32_t sBhu = smem_u32(sBh);
    const uint32_t sBlu = smem_u32(sBl);
    const int mrow = wid * 16;

    for (int kc = 0; kc < 4; kc++) {
#pragma unroll
        for (int i = 0; i < 2; i++) {
            int idx = i * 256 + tid;
            int row = idx >> 2, unit = idx & 3;
            int grow = mbase + row;
            uint4 vh = make_uint4(0, 0, 0, 0), vl = make_uint4(0, 0, 0, 0);
            if (grow < NN) {
                const float* ap = A + (size_t)grow * DD + kc * 32 + unit * 8;
                float4 f0 = *(const float4*)ap;
                float4 f1 = *(const float4*)(ap + 4);
                float y[8] = {f0.x, f0.y, f0.z, f0.w, f1.x, f1.y, f1.z, f1.w};
                int ch0 = kc * 32 + unit * 8;
                __half hh[8], hl[8];
#pragma unroll
                for (int j = 0; j < 8; j++) {
                    float f = y[j];
                    if (act) {
                        float2 c = sab[ch0 + j];
                        f = f * c.x + c.y;
                        f = (f >= 0.0f) ? f : 0.01f * f;
                    }
                    __half h = __float2half(f);
                    hh[j] = h;
                    hl[j] = __float2half(f - __half2float(h));
                }
                vh = make_uint4(pack2(hh[0], hh[1]), pack2(hh[2], hh[3]),
                                pack2(hh[4], hh[5]), pack2(hh[6], hh[7]));
                vl = make_uint4(pack2(hl[0], hl[1]), pack2(hl[2], hl[3]),
                                pack2(hl[4], hl[5]), pack2(hl[6], hl[7]));
            }
            *(uint4*)((char*)sAh + sw64(idx * 16)) = vh;
            *(uint4*)((char*)sAl + sw64(idx * 16)) = vl;
        }
#pragma unroll
        for (int i = 0; i < 2; i++) {
            int idx = i * 256 + tid;
            int row = idx >> 2, unit = idx & 3;
            size_t g = (size_t)(ntile * 128 + row) * DD + kc * 32 + unit * 8;
            *(uint4*)((char*)sBh + sw64(idx * 16)) = *(const uint4*)(g_wallh + g);
            *(uint4*)((char*)sBl + sw64(idx * 16)) = *(const uint4*)(g_walll + g);
        }
        __syncthreads();

#pragma unroll
        for (int t = 0; t < 2; t++) {
            uint32_t ah[4], al[4];
            uint32_t aoff = (uint32_t)(mrow + (lane & 15)) * 64 + t * 32 + ((lane >> 4) * 16);
            ldmatrix_x4(ah, sAhu + sw64(aoff));
            ldmatrix_x4(al, sAlu + sw64(aoff));
#pragma unroll
            for (int np = 0; np < 8; np++) {
                int mtx = lane >> 3;
                uint32_t boff = (uint32_t)(np * 16 + ((mtx >> 1) * 8) + (lane & 7)) * 64
                              + t * 32 + ((mtx & 1) * 16);
                uint32_t bh[4], bl[4];
                ldmatrix_x4(bh, sBhu + sw64(boff));
                ldmatrix_x4(bl, sBlu + sw64(boff));
                mma16816(acc[2 * np],     ah, bh);
                mma16816(acc[2 * np],     ah, bl);
                mma16816(acc[2 * np],     al, bh);
                mma16816(acc[2 * np + 1], ah, bh + 2);
                mma16816(acc[2 * np + 1], ah, bl + 2);
                mma16816(acc[2 * np + 1], al, bh + 2);
            }
        }
        __syncthreads();
    }

    const int r0 = mbase + mrow + (lane >> 2);
    const int cq = (lane & 3) * 2;
    if (ntile == 3) {
#pragma unroll
        for (int nt = 0; nt < 16; nt++) {
            int n = nt * 8 + cq;
            float b0 = sbias[n], b1 = sbias[n + 1];
            if (r0 < NN)
                *(float2*)(os + (size_t)r0 * DD + n) = make_float2(acc[nt][0] + b0, acc[nt][1] + b1);
            if (r0 + 8 < NN)
                *(float2*)(os + (size_t)(r0 + 8) * DD + n) = make_float2(acc[nt][2] + b0, acc[nt][3] + b1);
        }
    } else {
        __half* dst = (ntile == 0) ? oq : (ntile == 1) ? okk : ov;
#pragma unroll
        for (int nt = 0; nt < 16; nt++) {
            int n = nt * 8 + cq;
            float b0 = sbias[n], b1 = sbias[n + 1];
            if (r0 < NN)
                *(__half2*)(dst + (size_t)r0 * DD + n) = __floats2half2_rn(acc[nt][0] + b0, acc[nt][1] + b1);
            if (r0 + 8 < NN)
                *(__half2*)(dst + (size_t)(r0 + 8) * DD + n) = __floats2half2_rn(acc[nt][2] + b0, acc[nt][3] + b1);
        }
    }
}

// -------- edge GEMM (CSR order) + e store + fused alpha -------------------------
__global__ void __launch_bounds__(256, 2)
edge_gemm_mma(const float* __restrict__ bias) {
    __shared__ __align__(128) __half sA[128 * 64];
    __shared__ __align__(128) __half sB[128 * 64];
    __shared__ float sbias[128];

    const int tid  = threadIdx.x;
    const int wid  = tid >> 5;
    const int lane = tid & 31;
    const size_t tile = blockIdx.x;

    if (tid < 128) sbias[tid] = bias[tid];

    const uint4* Ag = (const uint4*)(g_ea16 + tile * 128 * EDD);
#pragma unroll
    for (int i = 0; i < 4; i++) {
        int idx = i * 256 + tid;
        uint4 val = Ag[idx];
        *(uint4*)((char*)sA + sw128(idx * 16)) = val;
    }
    const uint4* Bg = (const uint4*)g_wet;
#pragma unroll
    for (int i = 0; i < 4; i++) {
        int idx = i * 256 + tid;
        uint4 val = Bg[idx];
        *(uint4*)((char*)sB + sw128(idx * 16)) = val;
    }

    const int mrow = wid * 16;
    const int p0 = (int)tile * 128 + mrow + (lane >> 2);
    const int p1 = p0 + 8;
    const int src0 = g_srcp[p0], dst0 = g_dstp[p0];
    const int src1 = g_srcp[p1], dst1 = g_dstp[p1];

    __syncthreads();

    const uint32_t sAu = smem_u32(sA);
    const uint32_t sBu = smem_u32(sB);

    uint32_t afrag[4][4];
#pragma unroll
    for (int t = 0; t < 4; t++) {
        uint32_t off = (uint32_t)(mrow + (lane & 15)) * 128 + t * 32 + ((lane >> 4) * 16);
        ldmatrix_x4(afrag[t], sAu + sw128(off));
    }

    float acc[16][4];
#pragma unroll
    for (int i = 0; i < 16; i++)
#pragma unroll
        for (int j = 0; j < 4; j++) acc[i][j] = 0.0f;

#pragma unroll
    for (int t = 0; t < 4; t++) {
#pragma unroll
        for (int np = 0; np < 8; np++) {
            int mtx = lane >> 3;
            int n   = np * 16 + ((mtx >> 1) * 8) + (lane & 7);
            int kb  = t * 32 + ((mtx & 1) * 16);
            uint32_t b[4];
            ldmatrix_x4(b, sBu + sw128((uint32_t)n * 128 + kb));
            mma16816(acc[2 * np],     afrag[t], b);
            mma16816(acc[2 * np + 1], afrag[t], b + 2);
        }
    }

    const int cq = (lane & 3) * 2;
    const __half* q0 = g_q16 + (size_t)dst0 * DD;
    const __half* k0 = g_k16 + (size_t)src0 * DD;
    const __half* q1 = g_q16 + (size_t)dst1 * DD;
    const __half* k1 = g_k16 + (size_t)src1 * DD;
    __half* e0p = g_e + (size_t)p0 * DD;
    __half* e1p = g_e + (size_t)p1 * DD;

    float ps0[8], ps1[8];
#pragma unroll
    for (int h = 0; h < 8; h++) { ps0[h] = 0.0f; ps1[h] = 0.0f; }

#pragma unroll
    for (int nt = 0; nt < 16; nt++) {
        int n = nt * 8 + cq;
        int h = nt >> 1;
        float b0 = sbias[n], b1 = sbias[n + 1];
        float ea0 = acc[nt][0] + b0, ea1 = acc[nt][1] + b1;
        float eb0 = acc[nt][2] + b0, eb1 = acc[nt][3] + b1;
        *(__half2*)(e0p + n) = __floats2half2_rn(ea0, ea1);
        *(__half2*)(e1p + n) = __floats2half2_rn(eb0, eb1);
        float2 qa = __half22float2(*(const __half2*)(q0 + n));
        float2 ka = __half22float2(*(const __half2*)(k0 + n));
        float2 qb = __half22float2(*(const __half2*)(q1 + n));
        float2 kb = __half22float2(*(const __half2*)(k1 + n));
        ps0[h] += qa.x * (ka.x + ea0) + qa.y * (ka.y + ea1);
        ps1[h] += qb.x * (kb.x + eb0) + qb.y * (kb.y + eb1);
    }
#pragma unroll
    for (int h = 0; h < 8; h++) {
        ps0[h] += __shfl_xor_sync(0xFFFFFFFFu, ps0[h], 1);
        ps0[h] += __shfl_xor_sync(0xFFFFFFFFu, ps0[h], 2);
        ps1[h] += __shfl_xor_sync(0xFFFFFFFFu, ps1[h], 1);
        ps1[h] += __shfl_xor_sync(0xFFFFFFFFu, ps1[h], 2);
    }
    const int qid = lane & 3;
#pragma unroll
    for (int h = 0; h < 8; h++) {
        if ((h & 3) == qid) {
            g_alpha[(size_t)p0 * HH + h] = ps0[h] * 0.25f;
            g_alpha[(size_t)p1 * HH + h] = ps1[h] * 0.25f;
        }
    }
}

// ------------- per-node gather: softmax (no max shift) + msg sum + skip --------
__global__ void __launch_bounds__(128)
gather_kernel() {
    const int n   = blockIdx.x;
    const int tid = threadIdx.x;
    const int start = g_rowptr[n], end = g_rowptr[n + 1];
    const int i0 = tid >> 3, h8 = tid & 7;
    const int hch = tid >> 4;

    __shared__ float sex[16][8];
    __shared__ int   ssrc[16];
    __shared__ float sden[8];
    __shared__ __align__(16) __half sV[16 * 128];   // 4 KB
    __shared__ __align__(16) __half sE[16 * 128];   // 4 KB

    float msg = 0.0f, den = 0.0f;
    for (int base = start; base < end; base += 16) {
        int cnt = min(16, end - base);
        if (tid < cnt) ssrc[tid] = g_srcp[base + tid];
        if (i0 < cnt)
            sex[i0][h8] = __expf(g_alpha[(size_t)(base + i0) * HH + h8]);
        __syncthreads();

        {
            const uint4* src = (const uint4*)(g_e + (size_t)base * DD);
            uint4* dst = (uint4*)sE;
            for (int u = tid; u < cnt * 16; u += 128) dst[u] = src[u];
        }
        {
            uint4* dst = (uint4*)sV;
            for (int u = tid; u < cnt * 16; u += 128) {
                int row = u >> 4, c = u & 15;
                dst[u] = ((const uint4*)(g_v16 + (size_t)ssrc[row] * DD))[c];
            }
        }
        __syncthreads();

#pragma unroll 4
        for (int i = 0; i < cnt; i++) {
            float ex = sex[i][hch];
            msg += (__half2float(sV[i * 128 + tid]) + __half2float(sE[i * 128 + tid])) * ex;
        }
        if (tid < 8) {
            float s = 0.0f;
            for (int i = 0; i < cnt; i++) s += sex[i][tid];
            den += s;
        }
        __syncthreads();
    }
    if (tid < 8) sden[tid] = den;
    __syncthreads();

    float o = msg / (sden[hch] + 1e-16f) + g_skip[(size_t)n * DD + tid];
    g_out[(size_t)n * DD + tid] = o;
}

// ---- BN column sums (fp64, vectorized float4 loads) ----------------------------
__global__ void bn_sum_kernel() {
    // 128 threads: warp w covers full 128 channels (32 threads x float4).
    // rows covered in parallel: 256 blocks * 4 warps = 1024.
    const int tid  = threadIdx.x;
    const int lane = tid & 31, w = tid >> 5;
    const int c0 = lane * 4;

    double s[4]  = {0, 0, 0, 0};
    double s2[4] = {0, 0, 0, 0};
    for (int r = blockIdx.x * 4 + w; r < NN; r += 1024) {
        float4 f = *(const float4*)(g_out + (size_t)r * DD + c0);
        s[0] += f.x; s2[0] += (double)f.x * f.x;
        s[1] += f.y; s2[1] += (double)f.y * f.y;
        s[2] += f.z; s2[2] += (double)f.z * f.z;
        s[3] += f.w; s2[3] += (double)f.w * f.w;
    }
    __shared__ double red[4][256];   // [warp][ch*2-interleaved]
#pragma unroll
    for (int j = 0; j < 4; j++) {
        red[w][(c0 + j) * 2]     = s[j];
        red[w][(c0 + j) * 2 + 1] = s2[j];
    }
    __syncthreads();
    // 128 threads: thread t reduces ch=t across warps for both sums
    double a0 = red[0][tid * 2] + red[1][tid * 2] + red[2][tid * 2] + red[3][tid * 2];
    double a1 = red[0][tid * 2 + 1] + red[1][tid * 2 + 1] + red[2][tid * 2 + 1] + red[3][tid * 2 + 1];
    atomicAdd(&g_sums[tid], a0);
    atomicAdd(&g_sums[DD + tid], a1);
}

__global__ void bn_fin_kernel(const float* __restrict__ gamma,
                              const float* __restrict__ beta) {
    int ch = threadIdx.x;
    double mu  = g_sums[ch] / (double)NN;
    double var = g_sums[DD + ch] / (double)NN - mu * mu;
    double rs  = 1.0 / sqrt(var + 1e-5);
    float a = gamma[ch] * (float)rs;
    float b = beta[ch] - (float)mu * a;
    g_ab[ch] = make_float2(a, b);
}

// final BN apply + LeakyReLU -> harness output
__global__ void bn_apply_final(float* __restrict__ xo) {
    int idx = blockIdx.x * blockDim.x + threadIdx.x;
    if (idx >= NN * DD) return;
    int ch = idx & (DD - 1);
    float2 c = g_ab[ch];
    float y = g_out[idx] * c.x + c.y;
    xo[idx] = (y >= 0.0f) ? y : 0.01f * y;
}

// ---------------- driver -------------------------------------------------------
extern "C" void kernel_launch(void* const* d_in, const int* in_sizes, int n_in,
                              void* d_out, int out_size) {
    const float* x     = (const float*)d_in[0];
    const int*   ei    = (const int*)  d_in[1];
    const float* ea    = (const float*)d_in[2];
    const float* Wq    = (const float*)d_in[3];
    const float* bq    = (const float*)d_in[4];
    const float* Wk    = (const float*)d_in[5];
    const float* bk    = (const float*)d_in[6];
    const float* Wv    = (const float*)d_in[7];
    const float* bv    = (const float*)d_in[8];
    const float* We    = (const float*)d_in[9];
    const float* be    = (const float*)d_in[10];
    const float* Ws    = (const float*)d_in[11];
    const float* bs    = (const float*)d_in[12];
    const float* gamma = (const float*)d_in[13];
    const float* beta  = (const float*)d_in[14];
    float* out = (float*)d_out;

    __half *q, *k, *v;
    float *ob, *sk;
    cudaGetSymbolAddress((void**)&q,  g_q16);
    cudaGetSymbolAddress((void**)&k,  g_k16);
    cudaGetSymbolAddress((void**)&v,  g_v16);
    cudaGetSymbolAddress((void**)&ob, g_out);
    cudaGetSymbolAddress((void**)&sk, g_skip);

    const int edgeTiles      = EE / 128;                // 6250
    const int nodeGemmBlocks = ((NN + 127) / 128) * 4;  // 1564
    const int nodeB          = (NN + 255) / 256;        // 196
    const int prepBlocks     = (512 * DD + 255) / 256;  // 256

    // one-time per launch: CSR build, permutation, conversions
    csr_zero <<<nodeB, 256>>>();
    csr_hist <<<(EE + 255) / 256, 256>>>(ei);
    csr_scan1<<<nodeB, 256>>>();
    csr_scan2<<<1, 256>>>(nodeB);
    csr_scan3<<<nodeB, 256>>>();
    csr_fill <<<(EE + 255) / 256, 256>>>(ei);
    perm_idx_kernel<<<(EE + 255) / 256, 256>>>(ei);
    conv_ea_perm<<<(int)(((size_t)EE * 16 + 255) / 256), 256>>>(ea);

    for (int l = 0; l < LL; l++) {
        prep_kernel<<<prepBlocks, 256>>>(
            We + (size_t)l * EDD * DD,
            Wq + (size_t)l * DD * DD, Wk + (size_t)l * DD * DD,
            Wv + (size_t)l * DD * DD, Ws + (size_t)l * DD * DD,
            bq + l * DD, bk + l * DD, bv + l * DD, bs + l * DD);

        node_gemm_mma<<<nodeGemmBlocks, 256>>>((l == 0) ? x : ob, (l > 0) ? 1 : 0,
                                               q, k, v, sk);

        edge_gemm_mma<<<edgeTiles, 256>>>(be + l * DD);

        gather_kernel<<<NN, 128>>>();

        bn_sum_kernel<<<256, 128>>>();
        bn_fin_kernel<<<1, 128>>>(gamma + l * DD, beta + l * DD);
    }
    bn_apply_final<<<(NN * DD + 255) / 256, 256>>>(out);
}

// round 16
// speedup vs baseline: 1.8922x; 1.0245x over previous
#include <cuda_runtime.h>
#include <cuda_fp16.h>
#include <cstdint>

// Problem constants (fixed by the reference)
#define NN   50000
#define EE   800000
#define DD   128
#define HH   8
#define CC   16
#define EDD  64
#define LL   3

// ---------------- scratch (static device globals; no allocation) -------------
__device__ __half g_q16[NN * DD];     // q (fp16)
__device__ __half g_k16[NN * DD];     // k (fp16)
__device__ __half g_v16[NN * DD];     // v (fp16)
__device__ float  g_out [NN * DD];    // pre-BN activations of current layer
__device__ float  g_skip[NN * DD];    // skip (x@Ws+bs)
__device__ __half g_e  [(size_t)EE * DD];      // per-edge e (fp16, CSR order)
__device__ __half g_ea16[(size_t)EE * EDD];    // edge_attr fp16, CSR-permuted
__device__ __half g_wet [DD * EDD];            // We^T fp16 [n=128][k=64]
__device__ __half g_wallh[512 * DD];           // [Wq|Wk|Wv|Ws]^T hi
__device__ __half g_walll[512 * DD];           // lo part
__device__ float  g_ball [512];                // [bq|bk|bv|bs]
__device__ float  g_alpha[(size_t)EE * HH];    // raw scores (CSR order)
__device__ double g_sums[2 * DD];
__device__ float2 g_ab  [DD];
// CSR (dst-sorted edge order; edge_index is launch-constant)
__device__ int    g_deg   [NN];
__device__ int    g_cursor[NN];
__device__ int    g_rowptr[NN + 1];
__device__ int    g_eord  [EE];
__device__ int    g_srcp  [EE];      // src per CSR position
__device__ int    g_dstp  [EE];      // dst per CSR position
__device__ int    g_bsums [256];

// ---------------- helpers ----------------------------------------------------
__device__ __forceinline__ uint32_t smem_u32(const void* p) {
    uint32_t a;
    asm("{ .reg .u64 t; cvta.to.shared.u64 t, %1; cvt.u32.u64 %0, t; }" : "=r"(a) : "l"(p));
    return a;
}
__device__ __forceinline__ uint32_t sw128(uint32_t off) { return off ^ ((off >> 3) & 0x70); }
__device__ __forceinline__ uint32_t sw64 (uint32_t off) { return off ^ ((off >> 3) & 0x30); }
__device__ __forceinline__ uint32_t pack2(__half a, __half b) {
    __half2 t = __halves2half2(a, b);
    return *(const uint32_t*)&t;
}

__device__ __forceinline__ void ldmatrix_x4(uint32_t* r, uint32_t addr) {
    asm volatile("ldmatrix.sync.aligned.m8n8.x4.shared.b16 {%0,%1,%2,%3}, [%4];"
                 : "=r"(r[0]), "=r"(r[1]), "=r"(r[2]), "=r"(r[3]) : "r"(addr));
}
__device__ __forceinline__ void mma16816(float* c, const uint32_t* a, const uint32_t* b) {
    asm volatile("mma.sync.aligned.m16n8k16.row.col.f32.f16.f16.f32 "
                 "{%0,%1,%2,%3}, {%4,%5,%6,%7}, {%8,%9}, {%0,%1,%2,%3};"
                 : "+f"(c[0]), "+f"(c[1]), "+f"(c[2]), "+f"(c[3])
                 : "r"(a[0]), "r"(a[1]), "r"(a[2]), "r"(a[3]), "r"(b[0]), "r"(b[1]));
}

// ---------------- CSR build (once per launch) ----------------------------------
__global__ void csr_zero() {
    int i = blockIdx.x * blockDim.x + threadIdx.x;
    if (i < NN) { g_deg[i] = 0; g_cursor[i] = 0; }
}
__global__ void csr_hist(const int* __restrict__ ei) {
    int e = blockIdx.x * blockDim.x + threadIdx.x;
    if (e < EE) atomicAdd(&g_deg[ei[EE + e]], 1);
}
__global__ void csr_scan1() {
    __shared__ int s[256];
    int t = threadIdx.x;
    int i = blockIdx.x * 256 + t;
    int v = (i < NN) ? g_deg[i] : 0;
    s[t] = v;
    __syncthreads();
    for (int st = 1; st < 256; st <<= 1) {
        int x = (t >= st) ? s[t - st] : 0;
        __syncthreads();
        if (t >= st) s[t] += x;
        __syncthreads();
    }
    if (i < NN) g_rowptr[i] = s[t] - v;
    if (t == 255) g_bsums[blockIdx.x] = s[255];
}
__global__ void csr_scan2(int nblocks) {
    __shared__ int s[256];
    int t = threadIdx.x;
    int v = (t < nblocks) ? g_bsums[t] : 0;
    s[t] = v;
    __syncthreads();
    for (int st = 1; st < 256; st <<= 1) {
        int x = (t >= st) ? s[t - st] : 0;
        __syncthreads();
        if (t >= st) s[t] += x;
        __syncthreads();
    }
    if (t < nblocks) g_bsums[t] = s[t] - v;
}
__global__ void csr_scan3() {
    int i = blockIdx.x * blockDim.x + threadIdx.x;
    if (i < NN) g_rowptr[i] += g_bsums[i >> 8];
    if (i == 0) g_rowptr[NN] = EE;
}
__global__ void csr_fill(const int* __restrict__ ei) {
    int e = blockIdx.x * blockDim.x + threadIdx.x;
    if (e >= EE) return;
    int d = ei[EE + e];
    int pos = g_rowptr[d] + atomicAdd(&g_cursor[d], 1);
    g_eord[pos] = e;
}
__global__ void perm_idx_kernel(const int* __restrict__ ei) {
    int p = blockIdx.x * blockDim.x + threadIdx.x;
    if (p >= EE) return;
    int eid = g_eord[p];
    g_srcp[p] = ei[eid];
    g_dstp[p] = ei[EE + eid];
}
__global__ void conv_ea_perm(const float* __restrict__ ea) {
    int i = blockIdx.x * blockDim.x + threadIdx.x;   // over 4-float units
    int p = i >> 4;
    if (p >= EE) return;
    int off = (i & 15) * 4;
    int eid = g_eord[p];
    float4 f = *(const float4*)(ea + (size_t)eid * EDD + off);
    __half2 h01 = __floats2half2_rn(f.x, f.y);
    __half2 h23 = __floats2half2_rn(f.z, f.w);
    uint2 pk;
    pk.x = *(const unsigned*)&h01;
    pk.y = *(const unsigned*)&h23;
    *(uint2*)(g_ea16 + (size_t)p * EDD + off) = pk;
}

// ---------------- merged per-layer prep: sums init + We^T + Wall ----------------
__global__ void prep_kernel(const float* __restrict__ We,
                            const float* __restrict__ Wq, const float* __restrict__ Wk,
                            const float* __restrict__ Wv, const float* __restrict__ Ws,
                            const float* __restrict__ bq, const float* __restrict__ bk,
                            const float* __restrict__ bv, const float* __restrict__ bs) {
    int i = blockIdx.x * blockDim.x + threadIdx.x;
    if (i < 2 * DD) g_sums[i] = 0.0;
    if (i < DD * EDD) {
        int n = i / EDD, k = i % EDD;
        g_wet[i] = __float2half(We[k * DD + n]);
    }
    if (i < 512 * DD) {
        int ng = i / DD;
        int k  = i % DD;
        int mtx = ng >> 7, nloc = ng & 127;
        const float* W = (mtx == 0) ? Wq : (mtx == 1) ? Wk : (mtx == 2) ? Wv : Ws;
        float w = W[k * DD + nloc];
        __half h = __float2half(w);
        g_wallh[i] = h;
        g_walll[i] = __float2half(w - __half2float(h));
        if (i < 512) {
            int m2 = i >> 7, l2 = i & 127;
            const float* b = (m2 == 0) ? bq : (m2 == 1) ? bk : (m2 == 2) ? bv : bs;
            g_ball[i] = b[l2];
        }
    }
}

// ------------- fused node GEMM: BN affine + LeakyReLU + split during A load ----
__global__ void __launch_bounds__(256, 2)
node_gemm_mma(const float* __restrict__ A, int act,
              __half* __restrict__ oq, __half* __restrict__ okk,
              __half* __restrict__ ov, float* __restrict__ os) {
    __shared__ __align__(128) __half sAh[128 * 32];
    __shared__ __align__(128) __half sAl[128 * 32];
    __shared__ __align__(128) __half sBh[128 * 32];
    __shared__ __align__(128) __half sBl[128 * 32];
    __shared__ float sbias[128];
    __shared__ float2 sab[128];

    const int tid  = threadIdx.x;
    const int wid  = tid >> 5;
    const int lane = tid & 31;
    const int ntile = blockIdx.x & 3;
    const int mbase = (blockIdx.x >> 2) * 128;

    if (tid < 128) {
        sbias[tid] = g_ball[ntile * 128 + tid];
        sab[tid]   = act ? g_ab[tid] : make_float2(1.0f, 0.0f);
    }
    __syncthreads();

    float acc[16][4];
#pragma unroll
    for (int i = 0; i < 16; i++)
#pragma unroll
        for (int j = 0; j < 4; j++) acc[i][j] = 0.0f;

    const uint32_t sAhu = smem_u32(sAh);
    const uint32_t sAlu = smem_u32(sAl);
    const uint32_t sBhu = smem_u32(sBh);
    const uint32_t sBlu = smem_u32(sBl);
    const int mrow = wid * 16;

    for (int kc = 0; kc < 4; kc++) {
#pragma unroll
        for (int i = 0; i < 2; i++) {
            int idx = i * 256 + tid;
            int row = idx >> 2, unit = idx & 3;
            int grow = mbase + row;
            uint4 vh = make_uint4(0, 0, 0, 0), vl = make_uint4(0, 0, 0, 0);
            if (grow < NN) {
                const float* ap = A + (size_t)grow * DD + kc * 32 + unit * 8;
                float4 f0 = *(const float4*)ap;
                float4 f1 = *(const float4*)(ap + 4);
                float y[8] = {f0.x, f0.y, f0.z, f0.w, f1.x, f1.y, f1.z, f1.w};
                int ch0 = kc * 32 + unit * 8;
                __half hh[8], hl[8];
#pragma unroll
                for (int j = 0; j < 8; j++) {
                    float f = y[j];
                    if (act) {
                        float2 c = sab[ch0 + j];
                        f = f * c.x + c.y;
                        f = (f >= 0.0f) ? f : 0.01f * f;
                    }
                    __half h = __float2half(f);
                    hh[j] = h;
                    hl[j] = __float2half(f - __half2float(h));
                }
                vh = make_uint4(pack2(hh[0], hh[1]), pack2(hh[2], hh[3]),
                                pack2(hh[4], hh[5]), pack2(hh[6], hh[7]));
                vl = make_uint4(pack2(hl[0], hl[1]), pack2(hl[2], hl[3]),
                                pack2(hl[4], hl[5]), pack2(hl[6], hl[7]));
            }
            *(uint4*)((char*)sAh + sw64(idx * 16)) = vh;
            *(uint4*)((char*)sAl + sw64(idx * 16)) = vl;
        }
#pragma unroll
        for (int i = 0; i < 2; i++) {
            int idx = i * 256 + tid;
            int row = idx >> 2, unit = idx & 3;
            size_t g = (size_t)(ntile * 128 + row) * DD + kc * 32 + unit * 8;
            *(uint4*)((char*)sBh + sw64(idx * 16)) = *(const uint4*)(g_wallh + g);
            *(uint4*)((char*)sBl + sw64(idx * 16)) = *(const uint4*)(g_walll + g);
        }
        __syncthreads();

#pragma unroll
        for (int t = 0; t < 2; t++) {
            uint32_t ah[4], al[4];
            uint32_t aoff = (uint32_t)(mrow + (lane & 15)) * 64 + t * 32 + ((lane >> 4) * 16);
            ldmatrix_x4(ah, sAhu + sw64(aoff));
            ldmatrix_x4(al, sAlu + sw64(aoff));
#pragma unroll
            for (int np = 0; np < 8; np++) {
                int mtx = lane >> 3;
                uint32_t boff = (uint32_t)(np * 16 + ((mtx >> 1) * 8) + (lane & 7)) * 64
                              + t * 32 + ((mtx & 1) * 16);
                uint32_t bh[4], bl[4];
                ldmatrix_x4(bh, sBhu + sw64(boff));
                ldmatrix_x4(bl, sBlu + sw64(boff));
                mma16816(acc[2 * np],     ah, bh);
                mma16816(acc[2 * np],     ah, bl);
                mma16816(acc[2 * np],     al, bh);
                mma16816(acc[2 * np + 1], ah, bh + 2);
                mma16816(acc[2 * np + 1], ah, bl + 2);
                mma16816(acc[2 * np + 1], al, bh + 2);
            }
        }
        __syncthreads();
    }

    const int r0 = mbase + mrow + (lane >> 2);
    const int cq = (lane & 3) * 2;
    if (ntile == 3) {
#pragma unroll
        for (int nt = 0; nt < 16; nt++) {
            int n = nt * 8 + cq;
            float b0 = sbias[n], b1 = sbias[n + 1];
            if (r0 < NN)
                *(float2*)(os + (size_t)r0 * DD + n) = make_float2(acc[nt][0] + b0, acc[nt][1] + b1);
            if (r0 + 8 < NN)
                *(float2*)(os + (size_t)(r0 + 8) * DD + n) = make_float2(acc[nt][2] + b0, acc[nt][3] + b1);
        }
    } else {
        __half* dst = (ntile == 0) ? oq : (ntile == 1) ? okk : ov;
#pragma unroll
        for (int nt = 0; nt < 16; nt++) {
            int n = nt * 8 + cq;
            float b0 = sbias[n], b1 = sbias[n + 1];
            if (r0 < NN)
                *(__half2*)(dst + (size_t)r0 * DD + n) = __floats2half2_rn(acc[nt][0] + b0, acc[nt][1] + b1);
            if (r0 + 8 < NN)
                *(__half2*)(dst + (size_t)(r0 + 8) * DD + n) = __floats2half2_rn(acc[nt][2] + b0, acc[nt][3] + b1);
        }
    }
}

// -------- edge GEMM (CSR order) + e store + fused alpha -------------------------
__global__ void __launch_bounds__(256, 2)
edge_gemm_mma(const float* __restrict__ bias) {
    __shared__ __align__(128) __half sA[128 * 64];
    __shared__ __align__(128) __half sB[128 * 64];
    __shared__ float sbias[128];

    const int tid  = threadIdx.x;
    const int wid  = tid >> 5;
    const int lane = tid & 31;
    const size_t tile = blockIdx.x;

    if (tid < 128) sbias[tid] = bias[tid];

    const uint4* Ag = (const uint4*)(g_ea16 + tile * 128 * EDD);
#pragma unroll
    for (int i = 0; i < 4; i++) {
        int idx = i * 256 + tid;
        uint4 val = Ag[idx];
        *(uint4*)((char*)sA + sw128(idx * 16)) = val;
    }
    const uint4* Bg = (const uint4*)g_wet;
#pragma unroll
    for (int i = 0; i < 4; i++) {
        int idx = i * 256 + tid;
        uint4 val = Bg[idx];
        *(uint4*)((char*)sB + sw128(idx * 16)) = val;
    }

    const int mrow = wid * 16;
    const int p0 = (int)tile * 128 + mrow + (lane >> 2);
    const int p1 = p0 + 8;
    const int src0 = g_srcp[p0], dst0 = g_dstp[p0];
    const int src1 = g_srcp[p1], dst1 = g_dstp[p1];

    __syncthreads();

    const uint32_t sAu = smem_u32(sA);
    const uint32_t sBu = smem_u32(sB);

    uint32_t afrag[4][4];
#pragma unroll
    for (int t = 0; t < 4; t++) {
        uint32_t off = (uint32_t)(mrow + (lane & 15)) * 128 + t * 32 + ((lane >> 4) * 16);
        ldmatrix_x4(afrag[t], sAu + sw128(off));
    }

    float acc[16][4];
#pragma unroll
    for (int i = 0; i < 16; i++)
#pragma unroll
        for (int j = 0; j < 4; j++) acc[i][j] = 0.0f;

#pragma unroll
    for (int t = 0; t < 4; t++) {
#pragma unroll
        for (int np = 0; np < 8; np++) {
            int mtx = lane >> 3;
            int n   = np * 16 + ((mtx >> 1) * 8) + (lane & 7);
            int kb  = t * 32 + ((mtx & 1) * 16);
            uint32_t b[4];
            ldmatrix_x4(b, sBu + sw128((uint32_t)n * 128 + kb));
            mma16816(acc[2 * np],     afrag[t], b);
            mma16816(acc[2 * np + 1], afrag[t], b + 2);
        }
    }

    const int cq = (lane & 3) * 2;
    const __half* q0 = g_q16 + (size_t)dst0 * DD;
    const __half* k0 = g_k16 + (size_t)src0 * DD;
    const __half* q1 = g_q16 + (size_t)dst1 * DD;
    const __half* k1 = g_k16 + (size_t)src1 * DD;
    __half* e0p = g_e + (size_t)p0 * DD;
    __half* e1p = g_e + (size_t)p1 * DD;

    float ps0[8], ps1[8];
#pragma unroll
    for (int h = 0; h < 8; h++) { ps0[h] = 0.0f; ps1[h] = 0.0f; }

#pragma unroll
    for (int nt = 0; nt < 16; nt++) {
        int n = nt * 8 + cq;
        int h = nt >> 1;
        float b0 = sbias[n], b1 = sbias[n + 1];
        float ea0 = acc[nt][0] + b0, ea1 = acc[nt][1] + b1;
        float eb0 = acc[nt][2] + b0, eb1 = acc[nt][3] + b1;
        *(__half2*)(e0p + n) = __floats2half2_rn(ea0, ea1);
        *(__half2*)(e1p + n) = __floats2half2_rn(eb0, eb1);
        float2 qa = __half22float2(*(const __half2*)(q0 + n));
        float2 ka = __half22float2(*(const __half2*)(k0 + n));
        float2 qb = __half22float2(*(const __half2*)(q1 + n));
        float2 kb = __half22float2(*(const __half2*)(k1 + n));
        ps0[h] += qa.x * (ka.x + ea0) + qa.y * (ka.y + ea1);
        ps1[h] += qb.x * (kb.x + eb0) + qb.y * (kb.y + eb1);
    }
#pragma unroll
    for (int h = 0; h < 8; h++) {
        ps0[h] += __shfl_xor_sync(0xFFFFFFFFu, ps0[h], 1);
        ps0[h] += __shfl_xor_sync(0xFFFFFFFFu, ps0[h], 2);
        ps1[h] += __shfl_xor_sync(0xFFFFFFFFu, ps1[h], 1);
        ps1[h] += __shfl_xor_sync(0xFFFFFFFFu, ps1[h], 2);
    }
    const int qid = lane & 3;
#pragma unroll
    for (int h = 0; h < 8; h++) {
        if ((h & 3) == qid) {
            g_alpha[(size_t)p0 * HH + h] = ps0[h] * 0.25f;
            g_alpha[(size_t)p1 * HH + h] = ps1[h] * 0.25f;
        }
    }
}

// ---- per-node gather, warp-per-node: softmax (no max) + msg sum + skip ---------
// No smem, no block syncs. Each warp owns one node; lane owns 4 channels.
__global__ void __launch_bounds__(256)
gather_kernel() {
    const int wid  = threadIdx.x >> 5;
    const int lane = threadIdx.x & 31;
    const int n    = blockIdx.x * 8 + wid;
    if (n >= NN) return;
    const int start = g_rowptr[n], end = g_rowptr[n + 1];
    const int c0  = lane * 4;            // channel base
    const int hch = lane >> 2;           // head of these channels

    float m0 = 0.f, m1 = 0.f, m2 = 0.f, m3 = 0.f, den = 0.f;

    for (int p = start; p < end; p++) {
        // lanes 0..7 hold exp(alpha) for heads 0..7; broadcast to all lanes
        float a  = g_alpha[(size_t)p * HH + (lane & 7)];
        float exall = __expf(a);
        float ex = __shfl_sync(0xFFFFFFFFu, exall, hch);
        den += ex;

        int src = g_srcp[p];
        uint2 eraw = *(const uint2*)(g_e   + (size_t)p   * DD + c0);
        uint2 vraw = *(const uint2*)(g_v16 + (size_t)src * DD + c0);
        float2 e01 = __half22float2(*(const __half2*)&eraw.x);
        float2 e23 = __half22float2(*(const __half2*)&eraw.y);
        float2 v01 = __half22float2(*(const __half2*)&vraw.x);
        float2 v23 = __half22float2(*(const __half2*)&vraw.y);
        m0 += (v01.x + e01.x) * ex;
        m1 += (v01.y + e01.y) * ex;
        m2 += (v23.x + e23.x) * ex;
        m3 += (v23.y + e23.y) * ex;
    }

    float inv = 1.0f / (den + 1e-16f);
    const float* skp = g_skip + (size_t)n * DD + c0;
    float4 sk4 = *(const float4*)skp;
    float4 o;
    o.x = m0 * inv + sk4.x;
    o.y = m1 * inv + sk4.y;
    o.z = m2 * inv + sk4.z;
    o.w = m3 * inv + sk4.w;
    *(float4*)(g_out + (size_t)n * DD + c0) = o;
}

// ---- BN column sums (fp64, vectorized float4 loads) ----------------------------
__global__ void bn_sum_kernel() {
    const int tid  = threadIdx.x;
    const int lane = tid & 31, w = tid >> 5;
    const int c0 = lane * 4;

    double s[4]  = {0, 0, 0, 0};
    double s2[4] = {0, 0, 0, 0};
    for (int r = blockIdx.x * 4 + w; r < NN; r += 1024) {
        float4 f = *(const float4*)(g_out + (size_t)r * DD + c0);
        s[0] += f.x; s2[0] += (double)f.x * f.x;
        s[1] += f.y; s2[1] += (double)f.y * f.y;
        s[2] += f.z; s2[2] += (double)f.z * f.z;
        s[3] += f.w; s2[3] += (double)f.w * f.w;
    }
    __shared__ double red[4][256];
#pragma unroll
    for (int j = 0; j < 4; j++) {
        red[w][(c0 + j) * 2]     = s[j];
        red[w][(c0 + j) * 2 + 1] = s2[j];
    }
    __syncthreads();
    double a0 = red[0][tid * 2] + red[1][tid * 2] + red[2][tid * 2] + red[3][tid * 2];
    double a1 = red[0][tid * 2 + 1] + red[1][tid * 2 + 1] + red[2][tid * 2 + 1] + red[3][tid * 2 + 1];
    atomicAdd(&g_sums[tid], a0);
    atomicAdd(&g_sums[DD + tid], a1);
}

__global__ void bn_fin_kernel(const float* __restrict__ gamma,
                              const float* __restrict__ beta) {
    int ch = threadIdx.x;
    double mu  = g_sums[ch] / (double)NN;
    double var = g_sums[DD + ch] / (double)NN - mu * mu;
    double rs  = 1.0 / sqrt(var + 1e-5);
    float a = gamma[ch] * (float)rs;
    float b = beta[ch] - (float)mu * a;
    g_ab[ch] = make_float2(a, b);
}

// final BN apply + LeakyReLU -> harness output
__global__ void bn_apply_final(float* __restrict__ xo) {
    int idx = blockIdx.x * blockDim.x + threadIdx.x;
    if (idx >= NN * DD) return;
    int ch = idx & (DD - 1);
    float2 c = g_ab[ch];
    float y = g_out[idx] * c.x + c.y;
    xo[idx] = (y >= 0.0f) ? y : 0.01f * y;
}

// ---------------- driver -------------------------------------------------------
extern "C" void kernel_launch(void* const* d_in, const int* in_sizes, int n_in,
                              void* d_out, int out_size) {
    const float* x     = (const float*)d_in[0];
    const int*   ei    = (const int*)  d_in[1];
    const float* ea    = (const float*)d_in[2];
    const float* Wq    = (const float*)d_in[3];
    const float* bq    = (const float*)d_in[4];
    const float* Wk    = (const float*)d_in[5];
    const float* bk    = (const float*)d_in[6];
    const float* Wv    = (const float*)d_in[7];
    const float* bv    = (const float*)d_in[8];
    const float* We    = (const float*)d_in[9];
    const float* be    = (const float*)d_in[10];
    const float* Ws    = (const float*)d_in[11];
    const float* bs    = (const float*)d_in[12];
    const float* gamma = (const float*)d_in[13];
    const float* beta  = (const float*)d_in[14];
    float* out = (float*)d_out;

    __half *q, *k, *v;
    float *ob, *sk;
    cudaGetSymbolAddress((void**)&q,  g_q16);
    cudaGetSymbolAddress((void**)&k,  g_k16);
    cudaGetSymbolAddress((void**)&v,  g_v16);
    cudaGetSymbolAddress((void**)&ob, g_out);
    cudaGetSymbolAddress((void**)&sk, g_skip);

    const int edgeTiles      = EE / 128;                // 6250
    const int nodeGemmBlocks = ((NN + 127) / 128) * 4;  // 1564
    const int nodeB          = (NN + 255) / 256;        // 196
    const int prepBlocks     = (512 * DD + 255) / 256;  // 256
    const int gatherBlocks   = (NN + 7) / 8;            // 6250

    // one-time per launch: CSR build, permutation, conversions
    csr_zero <<<nodeB, 256>>>();
    csr_hist <<<(EE + 255) / 256, 256>>>(ei);
    csr_scan1<<<nodeB, 256>>>();
    csr_scan2<<<1, 256>>>(nodeB);
    csr_scan3<<<nodeB, 256>>>();
    csr_fill <<<(EE + 255) / 256, 256>>>(ei);
    perm_idx_kernel<<<(EE + 255) / 256, 256>>>(ei);
    conv_ea_perm<<<(int)(((size_t)EE * 16 + 255) / 256), 256>>>(ea);

    for (int l = 0; l < LL; l++) {
        prep_kernel<<<prepBlocks, 256>>>(
            We + (size_t)l * EDD * DD,
            Wq + (size_t)l * DD * DD, Wk + (size_t)l * DD * DD,
            Wv + (size_t)l * DD * DD, Ws + (size_t)l * DD * DD,
            bq + l * DD, bk + l * DD, bv + l * DD, bs + l * DD);

        node_gemm_mma<<<nodeGemmBlocks, 256>>>((l == 0) ? x : ob, (l > 0) ? 1 : 0,
                                               q, k, v, sk);

        edge_gemm_mma<<<edgeTiles, 256>>>(be + l * DD);

        gather_kernel<<<gatherBlocks, 256>>>();

        bn_sum_kernel<<<256, 128>>>();
        bn_fin_kernel<<<1, 128>>>(gamma + l * DD, beta + l * DD);
    }
    bn_apply_final<<<(NN * DD + 255) / 256, 256>>>(out);
}

// round 17
// speedup vs baseline: 2.0495x; 1.0831x over previous
#include <cuda_runtime.h>
#include <cuda_fp16.h>
#include <cstdint>

// Problem constants (fixed by the reference)
#define NN   50000
#define EE   800000
#define DD   128
#define HH   8
#define CC   16
#define EDD  64
#define LL   3

// ---------------- scratch (static device globals; no allocation) -------------
__device__ __half g_q16[NN * DD];     // q (fp16)
__device__ __half g_k16[NN * DD];     // k (fp16)
__device__ __half g_v16[NN * DD];     // v (fp16)
__device__ float  g_out [NN * DD];    // pre-BN activations of current layer
__device__ float  g_skip[NN * DD];    // skip (x@Ws+bs)
__device__ __half g_e  [(size_t)EE * DD];      // per-edge e (fp16, CSR order)
__device__ __half g_ea16[(size_t)EE * EDD];    // edge_attr fp16, CSR-permuted
__device__ __half g_wet [DD * EDD];            // We^T fp16 [n=128][k=64]
__device__ __half g_wallh[512 * DD];           // [Wq|Wk|Wv|Ws]^T hi
__device__ __half g_walll[512 * DD];           // lo part
__device__ float  g_ball [512];                // [bq|bk|bv|bs]
__device__ float  g_alpha[(size_t)EE * HH];    // raw scores (CSR order)
__device__ double g_sums[2 * DD];
__device__ float2 g_ab  [DD];
// CSR (dst-sorted edge order; edge_index is launch-constant)
__device__ int    g_deg   [NN];
__device__ int    g_cursor[NN];
__device__ int    g_rowptr[NN + 1];
__device__ int    g_eord  [EE];
__device__ int    g_srcp  [EE];      // src per CSR position
__device__ int    g_dstp  [EE];      // dst per CSR position
__device__ int    g_bsums [256];

// ---------------- helpers ----------------------------------------------------
__device__ __forceinline__ uint32_t smem_u32(const void* p) {
    uint32_t a;
    asm("{ .reg .u64 t; cvta.to.shared.u64 t, %1; cvt.u32.u64 %0, t; }" : "=r"(a) : "l"(p));
    return a;
}
__device__ __forceinline__ uint32_t sw128(uint32_t off) { return off ^ ((off >> 3) & 0x70); }
__device__ __forceinline__ uint32_t sw64 (uint32_t off) { return off ^ ((off >> 3) & 0x30); }
__device__ __forceinline__ uint32_t pack2(__half a, __half b) {
    __half2 t = __halves2half2(a, b);
    return *(const uint32_t*)&t;
}
__device__ __forceinline__ void cp_async16(uint32_t saddr, const void* gaddr) {
    asm volatile("cp.async.cg.shared.global [%0], [%1], 16;"
                 :: "r"(saddr), "l"(gaddr) : "memory");
}
#define CP_ASYNC_COMMIT() asm volatile("cp.async.commit_group;" ::: "memory")
#define CP_ASYNC_WAIT()   asm volatile("cp.async.wait_group 0;" ::: "memory")

__device__ __forceinline__ void ldmatrix_x4(uint32_t* r, uint32_t addr) {
    asm volatile("ldmatrix.sync.aligned.m8n8.x4.shared.b16 {%0,%1,%2,%3}, [%4];"
                 : "=r"(r[0]), "=r"(r[1]), "=r"(r[2]), "=r"(r[3]) : "r"(addr));
}
__device__ __forceinline__ void mma16816(float* c, const uint32_t* a, const uint32_t* b) {
    asm volatile("mma.sync.aligned.m16n8k16.row.col.f32.f16.f16.f32 "
                 "{%0,%1,%2,%3}, {%4,%5,%6,%7}, {%8,%9}, {%0,%1,%2,%3};"
                 : "+f"(c[0]), "+f"(c[1]), "+f"(c[2]), "+f"(c[3])
                 : "r"(a[0]), "r"(a[1]), "r"(a[2]), "r"(a[3]), "r"(b[0]), "r"(b[1]));
}

// ---------------- CSR build (once per launch) ----------------------------------
__global__ void csr_zero() {
    int i = blockIdx.x * blockDim.x + threadIdx.x;
    if (i < NN) { g_deg[i] = 0; g_cursor[i] = 0; }
}
__global__ void csr_hist(const int* __restrict__ ei) {
    int e = blockIdx.x * blockDim.x + threadIdx.x;
    if (e < EE) atomicAdd(&g_deg[ei[EE + e]], 1);
}
__global__ void csr_scan1() {
    __shared__ int s[256];
    int t = threadIdx.x;
    int i = blockIdx.x * 256 + t;
    int v = (i < NN) ? g_deg[i] : 0;
    s[t] = v;
    __syncthreads();
    for (int st = 1; st < 256; st <<= 1) {
        int x = (t >= st) ? s[t - st] : 0;
        __syncthreads();
        if (t >= st) s[t] += x;
        __syncthreads();
    }
    if (i < NN) g_rowptr[i] = s[t] - v;
    if (t == 255) g_bsums[blockIdx.x] = s[255];
}
__global__ void csr_scan2(int nblocks) {
    __shared__ int s[256];
    int t = threadIdx.x;
    int v = (t < nblocks) ? g_bsums[t] : 0;
    s[t] = v;
    __syncthreads();
    for (int st = 1; st < 256; st <<= 1) {
        int x = (t >= st) ? s[t - st] : 0;
        __syncthreads();
        if (t >= st) s[t] += x;
        __syncthreads();
    }
    if (t < nblocks) g_bsums[t] = s[t] - v;
}
__global__ void csr_scan3() {
    int i = blockIdx.x * blockDim.x + threadIdx.x;
    if (i < NN) g_rowptr[i] += g_bsums[i >> 8];
    if (i == 0) g_rowptr[NN] = EE;
}
// fill + write permuted src/dst in one pass
__global__ void csr_fill(const int* __restrict__ ei) {
    int e = blockIdx.x * blockDim.x + threadIdx.x;
    if (e >= EE) return;
    int s = ei[e];
    int d = ei[EE + e];
    int pos = g_rowptr[d] + atomicAdd(&g_cursor[d], 1);
    g_eord[pos] = e;
    g_srcp[pos] = s;
    g_dstp[pos] = d;
}
__global__ void conv_ea_perm(const float* __restrict__ ea) {
    int i = blockIdx.x * blockDim.x + threadIdx.x;   // over 4-float units
    int p = i >> 4;
    if (p >= EE) return;
    int off = (i & 15) * 4;
    int eid = g_eord[p];
    float4 f = *(const float4*)(ea + (size_t)eid * EDD + off);
    __half2 h01 = __floats2half2_rn(f.x, f.y);
    __half2 h23 = __floats2half2_rn(f.z, f.w);
    uint2 pk;
    pk.x = *(const unsigned*)&h01;
    pk.y = *(const unsigned*)&h23;
    *(uint2*)(g_ea16 + (size_t)p * EDD + off) = pk;
}

// ---------------- merged per-layer prep: sums init + We^T + Wall ----------------
__global__ void prep_kernel(const float* __restrict__ We,
                            const float* __restrict__ Wq, const float* __restrict__ Wk,
                            const float* __restrict__ Wv, const float* __restrict__ Ws,
                            const float* __restrict__ bq, const float* __restrict__ bk,
                            const float* __restrict__ bv, const float* __restrict__ bs) {
    int i = blockIdx.x * blockDim.x + threadIdx.x;
    if (i < 2 * DD) g_sums[i] = 0.0;
    if (i < DD * EDD) {
        int n = i / EDD, k = i % EDD;
        g_wet[i] = __float2half(We[k * DD + n]);
    }
    if (i < 512 * DD) {
        int ng = i / DD;
        int k  = i % DD;
        int mtx = ng >> 7, nloc = ng & 127;
        const float* W = (mtx == 0) ? Wq : (mtx == 1) ? Wk : (mtx == 2) ? Wv : Ws;
        float w = W[k * DD + nloc];
        __half h = __float2half(w);
        g_wallh[i] = h;
        g_walll[i] = __float2half(w - __half2float(h));
        if (i < 512) {
            int m2 = i >> 7, l2 = i & 127;
            const float* b = (m2 == 0) ? bq : (m2 == 1) ? bk : (m2 == 2) ? bv : bs;
            g_ball[i] = b[l2];
        }
    }
}

// ------------- fused node GEMM: BN affine + LeakyReLU + split during A load ----
__global__ void __launch_bounds__(256, 2)
node_gemm_mma(const float* __restrict__ A, int act,
              __half* __restrict__ oq, __half* __restrict__ okk,
              __half* __restrict__ ov, float* __restrict__ os) {
    __shared__ __align__(128) __half sAh[128 * 32];
    __shared__ __align__(128) __half sAl[128 * 32];
    __shared__ __align__(128) __half sBh[128 * 32];
    __shared__ __align__(128) __half sBl[128 * 32];
    __shared__ float sbias[128];
    __shared__ float2 sab[128];

    const int tid  = threadIdx.x;
    const int wid  = tid >> 5;
    const int lane = tid & 31;
    const int ntile = blockIdx.x & 3;
    const int mbase = (blockIdx.x >> 2) * 128;

    if (tid < 128) {
        sbias[tid] = g_ball[ntile * 128 + tid];
        sab[tid]   = act ? g_ab[tid] : make_float2(1.0f, 0.0f);
    }
    __syncthreads();

    float acc[16][4];
#pragma unroll
    for (int i = 0; i < 16; i++)
#pragma unroll
        for (int j = 0; j < 4; j++) acc[i][j] = 0.0f;

    const uint32_t sAhu = smem_u32(sAh);
    const uint32_t sAlu = smem_u32(sAl);
    const uint32_t sBhu = smem_u32(sBh);
    const uint32_t sBlu = smem_u32(sBl);
    const int mrow = wid * 16;

    for (int kc = 0; kc < 4; kc++) {
#pragma unroll
        for (int i = 0; i < 2; i++) {
            int idx = i * 256 + tid;
            int row = idx >> 2, unit = idx & 3;
            int grow = mbase + row;
            uint4 vh = make_uint4(0, 0, 0, 0), vl = make_uint4(0, 0, 0, 0);
            if (grow < NN) {
                const float* ap = A + (size_t)grow * DD + kc * 32 + unit * 8;
                float4 f0 = *(const float4*)ap;
                float4 f1 = *(const float4*)(ap + 4);
                float y[8] = {f0.x, f0.y, f0.z, f0.w, f1.x, f1.y, f1.z, f1.w};
                int ch0 = kc * 32 + unit * 8;
                __half hh[8], hl[8];
#pragma unroll
                for (int j = 0; j < 8; j++) {
                    float f = y[j];
                    if (act) {
                        float2 c = sab[ch0 + j];
                        f = f * c.x + c.y;
                        f = (f >= 0.0f) ? f : 0.01f * f;
                    }
                    __half h = __float2half(f);
                    hh[j] = h;
                    hl[j] = __float2half(f - __half2float(h));
                }
                vh = make_uint4(pack2(hh[0], hh[1]), pack2(hh[2], hh[3]),
                                pack2(hh[4], hh[5]), pack2(hh[6], hh[7]));
                vl = make_uint4(pack2(hl[0], hl[1]), pack2(hl[2], hl[3]),
                                pack2(hl[4], hl[5]), pack2(hl[6], hl[7]));
            }
            *(uint4*)((char*)sAh + sw64(idx * 16)) = vh;
            *(uint4*)((char*)sAl + sw64(idx * 16)) = vl;
        }
#pragma unroll
        for (int i = 0; i < 2; i++) {
            int idx = i * 256 + tid;
            int row = idx >> 2, unit = idx & 3;
            size_t g = (size_t)(ntile * 128 + row) * DD + kc * 32 + unit * 8;
            *(uint4*)((char*)sBh + sw64(idx * 16)) = *(const uint4*)(g_wallh + g);
            *(uint4*)((char*)sBl + sw64(idx * 16)) = *(const uint4*)(g_walll + g);
        }
        __syncthreads();

#pragma unroll
        for (int t = 0; t < 2; t++) {
            uint32_t ah[4], al[4];
            uint32_t aoff = (uint32_t)(mrow + (lane & 15)) * 64 + t * 32 + ((lane >> 4) * 16);
            ldmatrix_x4(ah, sAhu + sw64(aoff));
            ldmatrix_x4(al, sAlu + sw64(aoff));
#pragma unroll
            for (int np = 0; np < 8; np++) {
                int mtx = lane >> 3;
                uint32_t boff = (uint32_t)(np * 16 + ((mtx >> 1) * 8) + (lane & 7)) * 64
                              + t * 32 + ((mtx & 1) * 16);
                uint32_t bh[4], bl[4];
                ldmatrix_x4(bh, sBhu + sw64(boff));
                ldmatrix_x4(bl, sBlu + sw64(boff));
                mma16816(acc[2 * np],     ah, bh);
                mma16816(acc[2 * np],     ah, bl);
                mma16816(acc[2 * np],     al, bh);
                mma16816(acc[2 * np + 1], ah, bh + 2);
                mma16816(acc[2 * np + 1], ah, bl + 2);
                mma16816(acc[2 * np + 1], al, bh + 2);
            }
        }
        __syncthreads();
    }

    const int r0 = mbase + mrow + (lane >> 2);
    const int cq = (lane & 3) * 2;
    if (ntile == 3) {
#pragma unroll
        for (int nt = 0; nt < 16; nt++) {
            int n = nt * 8 + cq;
            float b0 = sbias[n], b1 = sbias[n + 1];
            if (r0 < NN)
                *(float2*)(os + (size_t)r0 * DD + n) = make_float2(acc[nt][0] + b0, acc[nt][1] + b1);
            if (r0 + 8 < NN)
                *(float2*)(os + (size_t)(r0 + 8) * DD + n) = make_float2(acc[nt][2] + b0, acc[nt][3] + b1);
        }
    } else {
        __half* dst = (ntile == 0) ? oq : (ntile == 1) ? okk : ov;
#pragma unroll
        for (int nt = 0; nt < 16; nt++) {
            int n = nt * 8 + cq;
            float b0 = sbias[n], b1 = sbias[n + 1];
            if (r0 < NN)
                *(__half2*)(dst + (size_t)r0 * DD + n) = __floats2half2_rn(acc[nt][0] + b0, acc[nt][1] + b1);
            if (r0 + 8 < NN)
                *(__half2*)(dst + (size_t)(r0 + 8) * DD + n) = __floats2half2_rn(acc[nt][2] + b0, acc[nt][3] + b1);
        }
    }
}

// -------- edge GEMM (CSR order) + e store + fused alpha (cp.async loads) --------
__global__ void __launch_bounds__(256, 2)
edge_gemm_mma(const float* __restrict__ bias) {
    __shared__ __align__(128) __half sA[128 * 64];
    __shared__ __align__(128) __half sB[128 * 64];
    __shared__ float sbias[128];

    const int tid  = threadIdx.x;
    const int wid  = tid >> 5;
    const int lane = tid & 31;
    const size_t tile = blockIdx.x;

    if (tid < 128) sbias[tid] = bias[tid];

    const uint32_t sAu = smem_u32(sA);
    const uint32_t sBu = smem_u32(sB);

    const uint4* Ag = (const uint4*)(g_ea16 + tile * 128 * EDD);
#pragma unroll
    for (int i = 0; i < 4; i++) {
        int idx = i * 256 + tid;
        cp_async16(sAu + sw128(idx * 16), Ag + idx);
    }
    const uint4* Bg = (const uint4*)g_wet;
#pragma unroll
    for (int i = 0; i < 4; i++) {
        int idx = i * 256 + tid;
        cp_async16(sBu + sw128(idx * 16), Bg + idx);
    }
    CP_ASYNC_COMMIT();

    // index loads overlap the async tile copies
    const int mrow = wid * 16;
    const int p0 = (int)tile * 128 + mrow + (lane >> 2);
    const int p1 = p0 + 8;
    const int src0 = g_srcp[p0], dst0 = g_dstp[p0];
    const int src1 = g_srcp[p1], dst1 = g_dstp[p1];

    CP_ASYNC_WAIT();
    __syncthreads();

    uint32_t afrag[4][4];
#pragma unroll
    for (int t = 0; t < 4; t++) {
        uint32_t off = (uint32_t)(mrow + (lane & 15)) * 128 + t * 32 + ((lane >> 4) * 16);
        ldmatrix_x4(afrag[t], sAu + sw128(off));
    }

    float acc[16][4];
#pragma unroll
    for (int i = 0; i < 16; i++)
#pragma unroll
        for (int j = 0; j < 4; j++) acc[i][j] = 0.0f;

#pragma unroll
    for (int t = 0; t < 4; t++) {
#pragma unroll
        for (int np = 0; np < 8; np++) {
            int mtx = lane >> 3;
            int n   = np * 16 + ((mtx >> 1) * 8) + (lane & 7);
            int kb  = t * 32 + ((mtx & 1) * 16);
            uint32_t b[4];
            ldmatrix_x4(b, sBu + sw128((uint32_t)n * 128 + kb));
            mma16816(acc[2 * np],     afrag[t], b);
            mma16816(acc[2 * np + 1], afrag[t], b + 2);
        }
    }

    const int cq = (lane & 3) * 2;
    const __half* q0 = g_q16 + (size_t)dst0 * DD;
    const __half* k0 = g_k16 + (size_t)src0 * DD;
    const __half* q1 = g_q16 + (size_t)dst1 * DD;
    const __half* k1 = g_k16 + (size_t)src1 * DD;
    __half* e0p = g_e + (size_t)p0 * DD;
    __half* e1p = g_e + (size_t)p1 * DD;

    float ps0[8], ps1[8];
#pragma unroll
    for (int h = 0; h < 8; h++) { ps0[h] = 0.0f; ps1[h] = 0.0f; }

#pragma unroll
    for (int nt = 0; nt < 16; nt++) {
        int n = nt * 8 + cq;
        int h = nt >> 1;
        float b0 = sbias[n], b1 = sbias[n + 1];
        float ea0 = acc[nt][0] + b0, ea1 = acc[nt][1] + b1;
        float eb0 = acc[nt][2] + b0, eb1 = acc[nt][3] + b1;
        *(__half2*)(e0p + n) = __floats2half2_rn(ea0, ea1);
        *(__half2*)(e1p + n) = __floats2half2_rn(eb0, eb1);
        float2 qa = __half22float2(*(const __half2*)(q0 + n));
        float2 ka = __half22float2(*(const __half2*)(k0 + n));
        float2 qb = __half22float2(*(const __half2*)(q1 + n));
        float2 kb = __half22float2(*(const __half2*)(k1 + n));
        ps0[h] += qa.x * (ka.x + ea0) + qa.y * (ka.y + ea1);
        ps1[h] += qb.x * (kb.x + eb0) + qb.y * (kb.y + eb1);
    }
#pragma unroll
    for (int h = 0; h < 8; h++) {
        ps0[h] += __shfl_xor_sync(0xFFFFFFFFu, ps0[h], 1);
        ps0[h] += __shfl_xor_sync(0xFFFFFFFFu, ps0[h], 2);
        ps1[h] += __shfl_xor_sync(0xFFFFFFFFu, ps1[h], 1);
        ps1[h] += __shfl_xor_sync(0xFFFFFFFFu, ps1[h], 2);
    }
    const int qid = lane & 3;
#pragma unroll
    for (int h = 0; h < 8; h++) {
        if ((h & 3) == qid) {
            g_alpha[(size_t)p0 * HH + h] = ps0[h] * 0.25f;
            g_alpha[(size_t)p1 * HH + h] = ps1[h] * 0.25f;
        }
    }
}

// ---- per-node gather, warp-per-node, 2-edge software pipeline -------------------
__global__ void __launch_bounds__(256)
gather_kernel() {
    const int wid  = threadIdx.x >> 5;
    const int lane = threadIdx.x & 31;
    const int n    = blockIdx.x * 8 + wid;
    if (n >= NN) return;
    const int start = g_rowptr[n], end = g_rowptr[n + 1];
    const int c0  = lane * 4;
    const int hch = lane >> 2;

    float m0 = 0.f, m1 = 0.f, m2 = 0.f, m3 = 0.f, den = 0.f;

    int p = start;
    for (; p + 1 < end; p += 2) {
        // issue all loads for both edges first (MLP), accumulate in edge order
        float a0 = g_alpha[(size_t)p * HH + (lane & 7)];
        float a1 = g_alpha[(size_t)(p + 1) * HH + (lane & 7)];
        int s0 = g_srcp[p], s1 = g_srcp[p + 1];
        uint2 er0 = *(const uint2*)(g_e   + (size_t)p * DD + c0);
        uint2 er1 = *(const uint2*)(g_e   + (size_t)(p + 1) * DD + c0);
        uint2 vr0 = *(const uint2*)(g_v16 + (size_t)s0 * DD + c0);
        uint2 vr1 = *(const uint2*)(g_v16 + (size_t)s1 * DD + c0);

        float ex0 = __shfl_sync(0xFFFFFFFFu, __expf(a0), hch);
        float ex1 = __shfl_sync(0xFFFFFFFFu, __expf(a1), hch);
        den += ex0;
        den += ex1;

        float2 e01, e23, v01, v23;
        e01 = __half22float2(*(const __half2*)&er0.x);
        e23 = __half22float2(*(const __half2*)&er0.y);
        v01 = __half22float2(*(const __half2*)&vr0.x);
        v23 = __half22float2(*(const __half2*)&vr0.y);
        m0 += (v01.x + e01.x) * ex0;
        m1 += (v01.y + e01.y) * ex0;
        m2 += (v23.x + e23.x) * ex0;
        m3 += (v23.y + e23.y) * ex0;
        e01 = __half22float2(*(const __half2*)&er1.x);
        e23 = __half22float2(*(const __half2*)&er1.y);
        v01 = __half22float2(*(const __half2*)&vr1.x);
        v23 = __half22float2(*(const __half2*)&vr1.y);
        m0 += (v01.x + e01.x) * ex1;
        m1 += (v01.y + e01.y) * ex1;
        m2 += (v23.x + e23.x) * ex1;
        m3 += (v23.y + e23.y) * ex1;
    }
    if (p < end) {
        float a  = g_alpha[(size_t)p * HH + (lane & 7)];
        int src = g_srcp[p];
        uint2 eraw = *(const uint2*)(g_e   + (size_t)p   * DD + c0);
        uint2 vraw = *(const uint2*)(g_v16 + (size_t)src * DD + c0);
        float ex = __shfl_sync(0xFFFFFFFFu, __expf(a), hch);
        den += ex;
        float2 e01 = __half22float2(*(const __half2*)&eraw.x);
        float2 e23 = __half22float2(*(const __half2*)&eraw.y);
        float2 v01 = __half22float2(*(const __half2*)&vraw.x);
        float2 v23 = __half22float2(*(const __half2*)&vraw.y);
        m0 += (v01.x + e01.x) * ex;
        m1 += (v01.y + e01.y) * ex;
        m2 += (v23.x + e23.x) * ex;
        m3 += (v23.y + e23.y) * ex;
    }

    float inv = 1.0f / (den + 1e-16f);
    float4 sk4 = *(const float4*)(g_skip + (size_t)n * DD + c0);
    float4 o;
    o.x = m0 * inv + sk4.x;
    o.y = m1 * inv + sk4.y;
    o.z = m2 * inv + sk4.z;
    o.w = m3 * inv + sk4.w;
    *(float4*)(g_out + (size_t)n * DD + c0) = o;
}

// ---- BN column sums (fp64, vectorized float4 loads) ----------------------------
__global__ void bn_sum_kernel() {
    const int tid  = threadIdx.x;
    const int lane = tid & 31, w = tid >> 5;
    const int c0 = lane * 4;

    double s[4]  = {0, 0, 0, 0};
    double s2[4] = {0, 0, 0, 0};
    for (int r = blockIdx.x * 4 + w; r < NN; r += 1024) {
        float4 f = *(const float4*)(g_out + (size_t)r * DD + c0);
        s[0] += f.x; s2[0] += (double)f.x * f.x;
        s[1] += f.y; s2[1] += (double)f.y * f.y;
        s[2] += f.z; s2[2] += (double)f.z * f.z;
        s[3] += f.w; s2[3] += (double)f.w * f.w;
    }
    __shared__ double red[4][256];
#pragma unroll
    for (int j = 0; j < 4; j++) {
        red[w][(c0 + j) * 2]     = s[j];
        red[w][(c0 + j) * 2 + 1] = s2[j];
    }
    __syncthreads();
    double a0 = red[0][tid * 2] + red[1][tid * 2] + red[2][tid * 2] + red[3][tid * 2];
    double a1 = red[0][tid * 2 + 1] + red[1][tid * 2 + 1] + red[2][tid * 2 + 1] + red[3][tid * 2 + 1];
    atomicAdd(&g_sums[tid], a0);
    atomicAdd(&g_sums[DD + tid], a1);
}

__global__ void bn_fin_kernel(const float* __restrict__ gamma,
                              const float* __restrict__ beta) {
    int ch = threadIdx.x;
    double mu  = g_sums[ch] / (double)NN;
    double var = g_sums[DD + ch] / (double)NN - mu * mu;
    double rs  = 1.0 / sqrt(var + 1e-5);
    float a = gamma[ch] * (float)rs;
    float b = beta[ch] - (float)mu * a;
    g_ab[ch] = make_float2(a, b);
}

// final BN apply + LeakyReLU -> harness output
__global__ void bn_apply_final(float* __restrict__ xo) {
    int idx = blockIdx.x * blockDim.x + threadIdx.x;
    if (idx >= NN * DD) return;
    int ch = idx & (DD - 1);
    float2 c = g_ab[ch];
    float y = g_out[idx] * c.x + c.y;
    xo[idx] = (y >= 0.0f) ? y : 0.01f * y;
}

// ---------------- driver -------------------------------------------------------
extern "C" void kernel_launch(void* const* d_in, const int* in_sizes, int n_in,
                              void* d_out, int out_size) {
    const float* x     = (const float*)d_in[0];
    const int*   ei    = (const int*)  d_in[1];
    const float* ea    = (const float*)d_in[2];
    const float* Wq    = (const float*)d_in[3];
    const float* bq    = (const float*)d_in[4];
    const float* Wk    = (const float*)d_in[5];
    const float* bk    = (const float*)d_in[6];
    const float* Wv    = (const float*)d_in[7];
    const float* bv    = (const float*)d_in[8];
    const float* We    = (const float*)d_in[9];
    const float* be    = (const float*)d_in[10];
    const float* Ws    = (const float*)d_in[11];
    const float* bs    = (const float*)d_in[12];
    const float* gamma = (const float*)d_in[13];
    const float* beta  = (const float*)d_in[14];
    float* out = (float*)d_out;

    __half *q, *k, *v;
    float *ob, *sk;
    cudaGetSymbolAddress((void**)&q,  g_q16);
    cudaGetSymbolAddress((void**)&k,  g_k16);
    cudaGetSymbolAddress((void**)&v,  g_v16);
    cudaGetSymbolAddress((void**)&ob, g_out);
    cudaGetSymbolAddress((void**)&sk, g_skip);

    const int edgeTiles      = EE / 128;                // 6250
    const int nodeGemmBlocks = ((NN + 127) / 128) * 4;  // 1564
    const int nodeB          = (NN + 255) / 256;        // 196
    const int prepBlocks     = (512 * DD + 255) / 256;  // 256
    const int gatherBlocks   = (NN + 7) / 8;            // 6250

    // one-time per launch: CSR build, permutation, conversions
    csr_zero <<<nodeB, 256>>>();
    csr_hist <<<(EE + 255) / 256, 256>>>(ei);
    csr_scan1<<<nodeB, 256>>>();
    csr_scan2<<<1, 256>>>(nodeB);
    csr_scan3<<<nodeB, 256>>>();
    csr_fill <<<(EE + 255) / 256, 256>>>(ei);
    conv_ea_perm<<<(int)(((size_t)EE * 16 + 255) / 256), 256>>>(ea);

    for (int l = 0; l < LL; l++) {
        prep_kernel<<<prepBlocks, 256>>>(
            We + (size_t)l * EDD * DD,
            Wq + (size_t)l * DD * DD, Wk + (size_t)l * DD * DD,
            Wv + (size_t)l * DD * DD, Ws + (size_t)l * DD * DD,
            bq + l * DD, bk + l * DD, bv + l * DD, bs + l * DD);

        node_gemm_mma<<<nodeGemmBlocks, 256>>>((l == 0) ? x : ob, (l > 0) ? 1 : 0,
                                               q, k, v, sk);

        edge_gemm_mma<<<edgeTiles, 256>>>(be + l * DD);

        gather_kernel<<<gatherBlocks, 256>>>();

        bn_sum_kernel<<<256, 128>>>();
        bn_fin_kernel<<<1, 128>>>(gamma + l * DD, beta + l * DD);
    }
    bn_apply_final<<<(NN * DD + 255) / 256, 256>>>(out);
}